// round 2
// baseline (speedup 1.0000x reference)
#include <cuda_runtime.h>
#include <math.h>

#define B_ 8
#define T_ 2048
#define C_ 512
#define H_ 64
#define NQT (T_ / 64)   // 32 query tiles per batch

// Scratch for Q,K,V projections (device globals: no allocations allowed)
__device__ __align__(16) float g_q[B_ * T_ * H_];
__device__ __align__(16) float g_k[B_ * T_ * H_];
__device__ __align__(16) float g_v[B_ * T_ * H_];

// ---------------------------------------------------------------------------
// Projection: out[b*T+t, h] = x[b*T+t, :] . W[:, h]   for W in {Wq, Wk, Wv}
// Tiled fp32 GEMM: 64x64 output tile, K-chunks of 16, 4x4 microtile/thread.
// grid = (256, 3), block = 256
// ---------------------------------------------------------------------------
__global__ void proj_kernel(const float* __restrict__ x,
                            const float* __restrict__ Wq,
                            const float* __restrict__ Wk,
                            const float* __restrict__ Wv) {
    __shared__ float sX[64][20];   // 64 rows x 16 K (pad to 20 -> rows 16B aligned)
    __shared__ float sW[16][64];

    const int which = blockIdx.y;
    const float* W = (which == 0) ? Wq : ((which == 1) ? Wk : Wv);
    float* out = (which == 0) ? g_q : ((which == 1) ? g_k : g_v);

    const int rowBase = blockIdx.x * 64;
    const int tid = threadIdx.x;
    const int tx = tid & 15;   // output col group
    const int ty = tid >> 4;   // output row group

    float acc[4][4] = {};

    for (int k0 = 0; k0 < C_; k0 += 16) {
        // X tile: 64x16 floats = 256 float4, one per thread
        {
            int r = tid >> 2, c4 = tid & 3;
            float4 v = *(const float4*)&x[(size_t)(rowBase + r) * C_ + k0 + c4 * 4];
            *(float4*)&sX[r][c4 * 4] = v;
        }
        // W tile: 16x64 floats = 256 float4
        {
            int r = tid >> 4, c4 = tid & 15;
            float4 v = *(const float4*)&W[(size_t)(k0 + r) * H_ + c4 * 4];
            *(float4*)&sW[r][c4 * 4] = v;
        }
        __syncthreads();

        #pragma unroll
        for (int kk = 0; kk < 16; kk++) {
            float4 b4 = *(float4*)&sW[kk][tx * 4];
            float a0 = sX[ty * 4 + 0][kk];
            float a1 = sX[ty * 4 + 1][kk];
            float a2 = sX[ty * 4 + 2][kk];
            float a3 = sX[ty * 4 + 3][kk];
            acc[0][0] += a0 * b4.x; acc[0][1] += a0 * b4.y; acc[0][2] += a0 * b4.z; acc[0][3] += a0 * b4.w;
            acc[1][0] += a1 * b4.x; acc[1][1] += a1 * b4.y; acc[1][2] += a1 * b4.z; acc[1][3] += a1 * b4.w;
            acc[2][0] += a2 * b4.x; acc[2][1] += a2 * b4.y; acc[2][2] += a2 * b4.z; acc[2][3] += a2 * b4.w;
            acc[3][0] += a3 * b4.x; acc[3][1] += a3 * b4.y; acc[3][2] += a3 * b4.z; acc[3][3] += a3 * b4.w;
        }
        __syncthreads();
    }

    #pragma unroll
    for (int i = 0; i < 4; i++) {
        float4 v = make_float4(acc[i][0], acc[i][1], acc[i][2], acc[i][3]);
        *(float4*)&out[(size_t)(rowBase + ty * 4 + i) * H_ + tx * 4] = v;
    }
}

// ---------------------------------------------------------------------------
// Flash attention, fp32, online softmax in registers (shfl row reductions).
// 64-query tiles x 64-key tiles, 4x4 microtile per thread.
// Threads with the same ty (query-row group) are 16 consecutive lanes, so
// row max/sum reduce with __shfl_xor_sync masks 1,2,4,8 (never crosses the
// 16-lane boundary). m/l stats live in registers, replicated across the 16
// lanes (reductions make them identical).
// Triangular balance: block j handles q-tiles j and (NQT-1-j): work = const 33.
// grid = (NQT/2, B), block = 256, dynamic smem = 69632 B
// ---------------------------------------------------------------------------
#define ROWP 68  // 64 + 4 pad: rows stay 16B aligned, kills bank conflicts

__global__ void attn_kernel(float* __restrict__ out) {
    extern __shared__ float sm[];
    float (*sQ)[ROWP] = (float(*)[ROWP])(sm);
    float (*sK)[ROWP] = (float(*)[ROWP])(sm + 64 * ROWP);
    float (*sV)[ROWP] = (float(*)[ROWP])(sm + 2 * 64 * ROWP);
    float (*sP)[ROWP] = (float(*)[ROWP])(sm + 3 * 64 * ROWP);

    const int b = blockIdx.y;
    const int tid = threadIdx.x;
    const int tx = tid & 15;
    const int ty = tid >> 4;

    for (int half = 0; half < 2; half++) {
        const int qt = (half == 0) ? (int)blockIdx.x : (NQT - 1 - (int)blockIdx.x);

        // Load Q tile (64x64)
        const float* Qg = g_q + ((size_t)b * T_ + qt * 64) * H_;
        for (int i = tid; i < 64 * 16; i += 256) {
            int r = i >> 4, c4 = i & 15;
            *(float4*)&sQ[r][c4 * 4] = *(const float4*)&Qg[(size_t)r * H_ + c4 * 4];
        }

        float acc[4][4] = {};
        float mrow[4], lrow[4];
        #pragma unroll
        for (int i = 0; i < 4; i++) { mrow[i] = -1e30f; lrow[i] = 0.0f; }
        __syncthreads();

        for (int kt = 0; kt <= qt; kt++) {
            const float* Kg = g_k + ((size_t)b * T_ + kt * 64) * H_;
            const float* Vg = g_v + ((size_t)b * T_ + kt * 64) * H_;
            for (int i = tid; i < 64 * 16; i += 256) {
                int r = i >> 4, c4 = i & 15;
                *(float4*)&sK[r][c4 * 4] = *(const float4*)&Kg[(size_t)r * H_ + c4 * 4];
                *(float4*)&sV[r][c4 * 4] = *(const float4*)&Vg[(size_t)r * H_ + c4 * 4];
            }
            __syncthreads();

            // S = Q K^T (4x4 microtile / thread), k unrolled by 4 via float4
            float s[4][4] = {};
            #pragma unroll
            for (int kk = 0; kk < 64; kk += 4) {
                float4 qa[4], kb[4];
                #pragma unroll
                for (int i = 0; i < 4; i++) qa[i] = *(float4*)&sQ[ty * 4 + i][kk];
                #pragma unroll
                for (int j = 0; j < 4; j++) kb[j] = *(float4*)&sK[tx * 4 + j][kk];
                #pragma unroll
                for (int i = 0; i < 4; i++)
                    #pragma unroll
                    for (int j = 0; j < 4; j++)
                        s[i][j] += qa[i].x * kb[j].x + qa[i].y * kb[j].y
                                 + qa[i].z * kb[j].z + qa[i].w * kb[j].w;
            }

            // Causal mask on the diagonal tile (key index > query index)
            if (kt == qt) {
                #pragma unroll
                for (int i = 0; i < 4; i++)
                    #pragma unroll
                    for (int j = 0; j < 4; j++)
                        if (tx * 4 + j > ty * 4 + i) s[i][j] = -1e30f;
            }

            // Register online softmax: per query row, reduce across 16 tx lanes
            #pragma unroll
            for (int i = 0; i < 4; i++) {
                float rmax = fmaxf(fmaxf(s[i][0], s[i][1]), fmaxf(s[i][2], s[i][3]));
                #pragma unroll
                for (int m = 1; m < 16; m <<= 1)
                    rmax = fmaxf(rmax, __shfl_xor_sync(0xffffffffu, rmax, m));
                float newm = fmaxf(mrow[i], rmax);
                float scale = __expf(mrow[i] - newm);
                float rsum = 0.0f;
                #pragma unroll
                for (int j = 0; j < 4; j++) {
                    float p = __expf(s[i][j] - newm);
                    s[i][j] = p;
                    rsum += p;
                }
                #pragma unroll
                for (int m = 1; m < 16; m <<= 1)
                    rsum += __shfl_xor_sync(0xffffffffu, rsum, m);
                lrow[i] = lrow[i] * scale + rsum;
                mrow[i] = newm;
                #pragma unroll
                for (int j = 0; j < 4; j++) acc[i][j] *= scale;
            }

            // Publish P for the P @ V GEMM
            #pragma unroll
            for (int i = 0; i < 4; i++)
                #pragma unroll
                for (int j = 0; j < 4; j++)
                    sP[ty * 4 + i][tx * 4 + j] = s[i][j];
            __syncthreads();

            // O += P @ V
            #pragma unroll 4
            for (int kk = 0; kk < 64; kk++) {
                float4 vb = *(float4*)&sV[kk][tx * 4];
                #pragma unroll
                for (int i = 0; i < 4; i++) {
                    float p = sP[ty * 4 + i][kk];   // broadcast across the 16 lanes
                    acc[i][0] += p * vb.x; acc[i][1] += p * vb.y;
                    acc[i][2] += p * vb.z; acc[i][3] += p * vb.w;
                }
            }
            __syncthreads();   // protect sK/sV/sP before next tile's loads
        }

        // Epilogue: divide by l, store
        float* Og = out + ((size_t)b * T_ + qt * 64) * H_;
        #pragma unroll
        for (int i = 0; i < 4; i++) {
            float inv = 1.0f / lrow[i];
            float4 v = make_float4(acc[i][0] * inv, acc[i][1] * inv,
                                   acc[i][2] * inv, acc[i][3] * inv);
            *(float4*)&Og[(size_t)(ty * 4 + i) * H_ + tx * 4] = v;
        }
        __syncthreads();   // smem reused by next half
    }
}

// ---------------------------------------------------------------------------
// Harness entry. Inputs (metadata order): x [B,T,C], Wq, Wk, Wv [C,H].
// Output: [B,T,H] float32.
// ---------------------------------------------------------------------------
extern "C" void kernel_launch(void* const* d_in, const int* in_sizes, int n_in,
                              void* d_out, int out_size) {
    const float* x  = (const float*)d_in[0];
    const float* Wq = (const float*)d_in[1];
    const float* Wk = (const float*)d_in[2];
    const float* Wv = (const float*)d_in[3];
    float* out = (float*)d_out;

    (void)in_sizes; (void)n_in; (void)out_size;

    const int attn_smem = 4 * 64 * ROWP * (int)sizeof(float); // 69632 B
    // Host-side attribute set: not a stream op, safe under graph capture.
    cudaFuncSetAttribute(attn_kernel, cudaFuncAttributeMaxDynamicSharedMemorySize,
                         attn_smem);

    proj_kernel<<<dim3((B_ * T_) / 64, 3), 256>>>(x, Wq, Wk, Wv);
    attn_kernel<<<dim3(NQT / 2, B_), 256, attn_smem>>>(out);
}

// round 3
// speedup vs baseline: 1.5059x; 1.5059x over previous
#include <cuda_runtime.h>
#include <math.h>

#define B_ 8
#define T_ 2048
#define C_ 512
#define H_ 64
#define NQT128 (T_ / 128)     // 16 q-tiles of 128 rows
#define NPAIR (NQT128 / 2)    // 8 balanced pairs

// Scratch (device globals: no allocations allowed)
__device__ __align__(16) float g_q[B_ * T_ * H_];
__device__ __align__(16) float g_k[B_ * T_ * H_];
__device__ __align__(16) float g_v[B_ * T_ * H_];
// split-K partials: [half][b][t] stats and [half][b][t][h] unnormalized O
__device__ __align__(16) float g_pm[2][B_][T_];
__device__ __align__(16) float g_pl[2][B_][T_];
__device__ __align__(16) float g_po[2][B_][T_][H_];

// ---- packed f32x2 helpers (sm_100+) ----
typedef unsigned long long u64t;
__device__ __forceinline__ u64t ffma2(u64t a, u64t b, u64t c) {
    u64t d; asm("fma.rn.f32x2 %0, %1, %2, %3;" : "=l"(d) : "l"(a), "l"(b), "l"(c));
    return d;
}
__device__ __forceinline__ u64t fmul2(u64t a, u64t b) {
    u64t d; asm("mul.rn.f32x2 %0, %1, %2;" : "=l"(d) : "l"(a), "l"(b));
    return d;
}
__device__ __forceinline__ float2 u2f(u64t v) {
    float2 f; asm("mov.b64 {%0, %1}, %2;" : "=f"(f.x), "=f"(f.y) : "l"(v));
    return f;
}
__device__ __forceinline__ u64t f2u(float x, float y) {
    u64t v; asm("mov.b64 %0, {%1, %2};" : "=l"(v) : "f"(x), "f"(y));
    return v;
}

// ---------------------------------------------------------------------------
// Projection (unchanged from R2: measured at fp32-FMA roofline, ~80us)
// ---------------------------------------------------------------------------
__global__ void proj_kernel(const float* __restrict__ x,
                            const float* __restrict__ Wq,
                            const float* __restrict__ Wk,
                            const float* __restrict__ Wv) {
    __shared__ float sX[64][20];
    __shared__ float sW[16][64];

    const int which = blockIdx.y;
    const float* W = (which == 0) ? Wq : ((which == 1) ? Wk : Wv);
    float* out = (which == 0) ? g_q : ((which == 1) ? g_k : g_v);

    const int rowBase = blockIdx.x * 64;
    const int tid = threadIdx.x;
    const int tx = tid & 15;
    const int ty = tid >> 4;

    float acc[4][4] = {};

    for (int k0 = 0; k0 < C_; k0 += 16) {
        {
            int r = tid >> 2, c4 = tid & 3;
            float4 v = *(const float4*)&x[(size_t)(rowBase + r) * C_ + k0 + c4 * 4];
            *(float4*)&sX[r][c4 * 4] = v;
        }
        {
            int r = tid >> 4, c4 = tid & 15;
            float4 v = *(const float4*)&W[(size_t)(k0 + r) * H_ + c4 * 4];
            *(float4*)&sW[r][c4 * 4] = v;
        }
        __syncthreads();

        #pragma unroll
        for (int kk = 0; kk < 16; kk++) {
            float4 b4 = *(float4*)&sW[kk][tx * 4];
            float a0 = sX[ty * 4 + 0][kk];
            float a1 = sX[ty * 4 + 1][kk];
            float a2 = sX[ty * 4 + 2][kk];
            float a3 = sX[ty * 4 + 3][kk];
            acc[0][0] += a0 * b4.x; acc[0][1] += a0 * b4.y; acc[0][2] += a0 * b4.z; acc[0][3] += a0 * b4.w;
            acc[1][0] += a1 * b4.x; acc[1][1] += a1 * b4.y; acc[1][2] += a1 * b4.z; acc[1][3] += a1 * b4.w;
            acc[2][0] += a2 * b4.x; acc[2][1] += a2 * b4.y; acc[2][2] += a2 * b4.z; acc[2][3] += a2 * b4.w;
            acc[3][0] += a3 * b4.x; acc[3][1] += a3 * b4.y; acc[3][2] += a3 * b4.z; acc[3][3] += a3 * b4.w;
        }
        __syncthreads();
    }

    #pragma unroll
    for (int i = 0; i < 4; i++) {
        float4 v = make_float4(acc[i][0], acc[i][1], acc[i][2], acc[i][3]);
        *(float4*)&out[(size_t)(rowBase + ty * 4 + i) * H_ + tx * 4] = v;
    }
}

// ---------------------------------------------------------------------------
// Flash attention main pass. q-tile = 128 rows, key-tile = 64.
// 256 threads (16x16): thread (ty,tx) owns rows ty*8+i (i<8),
//   S keys   {tx+16j, j<4}  (strided: conflict-free LDS.128 on sK, stride 68==4 banks)
//   O heads  {tx+16c, c<4}  (strided: conflict-free LDS.64 on sVT, stride 66==2 banks)
// All inner FMAs are fma.rn.f32x2 paired along k; accumulators hold
// (even-k, odd-k) partials, collapsed at the end.
// Split-K: half hf processes kt in [0,qt+1) or [qt+1,2qt+2) -> exactly qt+1
// units each; pair (p, 15-p) makes every block 17 units. grid=(8,2,8).
// ---------------------------------------------------------------------------
#define QROWS 128
#define KKEYS 64
#define ROWP 68    // 68 % 32 == 4 banks/row; 272B rows -> 16B aligned
#define VROWP 66   // 66 % 32 == 2 banks/row; 264B rows -> 8B aligned

__global__ void __launch_bounds__(256, 1) attn_kernel() {
    extern __shared__ float sm[];
    float (*sQ)[ROWP]   = (float(*)[ROWP])sm;
    float (*sK)[ROWP]   = (float(*)[ROWP])(sm + QROWS * ROWP);
    float (*sVT)[VROWP] = (float(*)[VROWP])(sm + QROWS * ROWP + KKEYS * ROWP);
    float (*sP)[ROWP]   = (float(*)[ROWP])(sm + QROWS * ROWP + KKEYS * ROWP + H_ * VROWP);

    const int pair = blockIdx.x;   // 0..7
    const int hf   = blockIdx.y;   // 0..1  key-range half
    const int b    = blockIdx.z;   // batch
    const int tid  = threadIdx.x;
    const int tx   = tid & 15;
    const int ty   = tid >> 4;

    for (int side = 0; side < 2; side++) {
        const int qt = side ? (NQT128 - 1 - pair) : pair;

        // Load Q tile (128x64)
        const float* Qg = g_q + ((size_t)b * T_ + qt * QROWS) * H_;
        for (int i = tid; i < QROWS * (H_ / 4); i += 256) {
            int r = i >> 4, c4 = i & 15;
            *(float4*)&sQ[r][c4 * 4] = *(const float4*)&Qg[(size_t)r * H_ + c4 * 4];
        }

        u64t acc2[8][4];               // (even-k, odd-k) partial O sums
        float mrow[8], lrow[8];
        #pragma unroll
        for (int i = 0; i < 8; i++) {
            mrow[i] = -1e30f; lrow[i] = 0.0f;
            #pragma unroll
            for (int c = 0; c < 4; c++) acc2[i][c] = 0ull;
        }
        __syncthreads();

        const int kt0 = hf ? (qt + 1)     : 0;
        const int kt1 = hf ? (2 * qt + 2) : (qt + 1);
        for (int kt = kt0; kt < kt1; kt++) {
            // Load K tile [64 keys][64 h]
            const float* Kg = g_k + ((size_t)b * T_ + kt * KKEYS) * H_;
            for (int i = tid; i < KKEYS * (H_ / 4); i += 256) {
                int r = i >> 4, c4 = i & 15;
                *(float4*)&sK[r][c4 * 4] = *(const float4*)&Kg[(size_t)r * H_ + c4 * 4];
            }
            // Load V tile transposed: sVT[h][key]
            const float* Vg = g_v + ((size_t)b * T_ + kt * KKEYS) * H_;
            for (int i = tid; i < KKEYS * (H_ / 4); i += 256) {
                int r = i >> 4, c4 = i & 15;
                float4 v = *(const float4*)&Vg[(size_t)r * H_ + c4 * 4];
                sVT[c4 * 4 + 0][r] = v.x; sVT[c4 * 4 + 1][r] = v.y;
                sVT[c4 * 4 + 2][r] = v.z; sVT[c4 * 4 + 3][r] = v.w;
            }
            __syncthreads();

            // ---- S = Q K^T, k-paired f32x2 ----
            u64t s2[8][4];
            #pragma unroll
            for (int i = 0; i < 8; i++)
                #pragma unroll
                for (int j = 0; j < 4; j++) s2[i][j] = 0ull;

            #pragma unroll
            for (int kk = 0; kk < H_; kk += 4) {
                ulonglong2 kb[4];
                #pragma unroll
                for (int j = 0; j < 4; j++)
                    kb[j] = *(const ulonglong2*)&sK[tx + 16 * j][kk];
                #pragma unroll
                for (int i = 0; i < 8; i++) {
                    ulonglong2 qa = *(const ulonglong2*)&sQ[ty * 8 + i][kk];
                    #pragma unroll
                    for (int j = 0; j < 4; j++) {
                        s2[i][j] = ffma2(qa.x, kb[j].x, s2[i][j]);
                        s2[i][j] = ffma2(qa.y, kb[j].y, s2[i][j]);
                    }
                }
            }

            // ---- collapse pairs, causal mask, online softmax ----
            const bool diag = (kt >= 2 * qt);    // only last two tiles cross diagonal
            float s[8][4];
            #pragma unroll
            for (int i = 0; i < 8; i++) {
                const int row = qt * QROWS + ty * 8 + i;
                #pragma unroll
                for (int j = 0; j < 4; j++) {
                    float2 f = u2f(s2[i][j]);
                    s[i][j] = f.x + f.y;
                    if (diag) {
                        int key = kt * KKEYS + tx + 16 * j;
                        if (key > row) s[i][j] = -1e30f;
                    }
                }
            }
            #pragma unroll
            for (int i = 0; i < 8; i++) {
                float rmax = fmaxf(fmaxf(s[i][0], s[i][1]), fmaxf(s[i][2], s[i][3]));
                #pragma unroll
                for (int msk = 1; msk < 16; msk <<= 1)
                    rmax = fmaxf(rmax, __shfl_xor_sync(0xffffffffu, rmax, msk));
                float newm = fmaxf(mrow[i], rmax);
                float scale = __expf(mrow[i] - newm);
                float rsum = 0.0f;
                #pragma unroll
                for (int j = 0; j < 4; j++) {
                    float p = __expf(s[i][j] - newm);
                    s[i][j] = p;
                    rsum += p;
                }
                #pragma unroll
                for (int msk = 1; msk < 16; msk <<= 1)
                    rsum += __shfl_xor_sync(0xffffffffu, rsum, msk);
                lrow[i] = lrow[i] * scale + rsum;
                mrow[i] = newm;
                u64t sc2 = f2u(scale, scale);
                #pragma unroll
                for (int c = 0; c < 4; c++) acc2[i][c] = fmul2(acc2[i][c], sc2);
                #pragma unroll
                for (int j = 0; j < 4; j++) sP[ty * 8 + i][tx + 16 * j] = s[i][j];
            }
            __syncthreads();

            // ---- O += P @ V, k-paired f32x2 (P pairs contiguous, V transposed) ----
            #pragma unroll 2
            for (int kk = 0; kk < KKEYS; kk += 2) {
                u64t vb[4];
                #pragma unroll
                for (int c = 0; c < 4; c++)
                    vb[c] = *(const u64t*)&sVT[tx + 16 * c][kk];
                #pragma unroll
                for (int i = 0; i < 8; i++) {
                    u64t p2 = *(const u64t*)&sP[ty * 8 + i][kk];
                    #pragma unroll
                    for (int c = 0; c < 4; c++)
                        acc2[i][c] = ffma2(p2, vb[c], acc2[i][c]);
                }
            }
            __syncthreads();   // protect sK/sVT/sP before next tile's loads
        }

        // ---- write split-K partials (merge kernel normalizes) ----
        const int rowg = qt * QROWS + ty * 8;
        if (tx == 0) {
            #pragma unroll
            for (int i = 0; i < 8; i++) {
                g_pm[hf][b][rowg + i] = mrow[i];
                g_pl[hf][b][rowg + i] = lrow[i];
            }
        }
        #pragma unroll
        for (int i = 0; i < 8; i++) {
            #pragma unroll
            for (int c = 0; c < 4; c++) {
                float2 f = u2f(acc2[i][c]);
                g_po[hf][b][rowg + i][tx + 16 * c] = f.x + f.y;
            }
        }
        // next side's sQ load is safe: all threads passed the kt-loop's last
        // __syncthreads() and nothing reads sQ after it.
    }
}

// ---------------------------------------------------------------------------
// Merge: out = (e0*O0 + e1*O1) / (e0*l0 + e1*l1), e_h = exp(m_h - max(m0,m1)).
// Fully-masked halves have m=-1e30 -> e underflows to exactly 0.
// grid = 1024, block = 256: one thread per (row, float4 chunk).
// ---------------------------------------------------------------------------
__global__ void merge_kernel(float* __restrict__ out) {
    int idx = blockIdx.x * 256 + threadIdx.x;   // 0 .. 16384*16-1
    int row = idx >> 4;
    int c4  = idx & 15;
    int b = row >> 11;
    int t = row & 2047;

    float m0 = g_pm[0][b][t], m1 = g_pm[1][b][t];
    float l0 = g_pl[0][b][t], l1 = g_pl[1][b][t];
    float M  = fmaxf(m0, m1);
    float e0 = __expf(m0 - M), e1 = __expf(m1 - M);
    float inv = 1.0f / (l0 * e0 + l1 * e1);

    float4 a0 = *(const float4*)&g_po[0][b][t][c4 * 4];
    float4 a1 = *(const float4*)&g_po[1][b][t][c4 * 4];
    float4 o;
    o.x = (a0.x * e0 + a1.x * e1) * inv;
    o.y = (a0.y * e0 + a1.y * e1) * inv;
    o.z = (a0.z * e0 + a1.z * e1) * inv;
    o.w = (a0.w * e0 + a1.w * e1) * inv;
    *(float4*)&out[(size_t)row * H_ + c4 * 4] = o;
}

// ---------------------------------------------------------------------------
// Harness entry. Inputs: x [B,T,C], Wq, Wk, Wv [C,H]. Output: [B,T,H] f32.
// ---------------------------------------------------------------------------
extern "C" void kernel_launch(void* const* d_in, const int* in_sizes, int n_in,
                              void* d_out, int out_size) {
    const float* x  = (const float*)d_in[0];
    const float* Wq = (const float*)d_in[1];
    const float* Wk = (const float*)d_in[2];
    const float* Wv = (const float*)d_in[3];
    float* out = (float*)d_out;
    (void)in_sizes; (void)n_in; (void)out_size;

    const int attn_smem =
        (QROWS * ROWP + KKEYS * ROWP + H_ * VROWP + QROWS * ROWP) * (int)sizeof(float); // 103936 B
    cudaFuncSetAttribute(attn_kernel, cudaFuncAttributeMaxDynamicSharedMemorySize,
                         attn_smem);

    proj_kernel<<<dim3((B_ * T_) / 64, 3), 256>>>(x, Wq, Wk, Wv);
    attn_kernel<<<dim3(NPAIR, 2, B_), 256, attn_smem>>>();
    merge_kernel<<<(B_ * T_ * (H_ / 4)) / 256, 256>>>(out);
}

// round 4
// speedup vs baseline: 1.5383x; 1.0215x over previous
#include <cuda_runtime.h>
#include <math.h>

#define B_ 8
#define T_ 2048
#define C_ 512
#define H_ 64
#define NQT128 (T_ / 128)     // 16 q-tiles of 128 rows
#define NPAIR (NQT128 / 2)    // 8 balanced pairs

// Scratch (device globals: no allocations allowed)
__device__ __align__(16) float g_q[B_ * T_ * H_];
__device__ __align__(16) float g_k[B_ * T_ * H_];
__device__ __align__(16) float g_v[B_ * T_ * H_];
// split-K partials: [half][b][t] stats and [half][b][t][h] unnormalized O
__device__ __align__(16) float g_pm[2][B_][T_];
__device__ __align__(16) float g_pl[2][B_][T_];
__device__ __align__(16) float g_po[2][B_][T_][H_];

// ---- packed f32x2 helpers (sm_100+) ----
typedef unsigned long long u64t;
__device__ __forceinline__ u64t ffma2(u64t a, u64t b, u64t c) {
    u64t d; asm("fma.rn.f32x2 %0, %1, %2, %3;" : "=l"(d) : "l"(a), "l"(b), "l"(c));
    return d;
}
__device__ __forceinline__ u64t fmul2(u64t a, u64t b) {
    u64t d; asm("mul.rn.f32x2 %0, %1, %2;" : "=l"(d) : "l"(a), "l"(b));
    return d;
}
__device__ __forceinline__ float2 u2f(u64t v) {
    float2 f; asm("mov.b64 {%0, %1}, %2;" : "=f"(f.x), "=f"(f.y) : "l"(v));
    return f;
}
__device__ __forceinline__ u64t f2u(float x, float y) {
    u64t v; asm("mov.b64 %0, {%1, %2};" : "=l"(v) : "f"(x), "f"(y));
    return v;
}

// ---------------------------------------------------------------------------
// Projection v2: out[row, n] = x[row, :] . W[:, n], one W per blockIdx.y.
// 128x64 output tile, K-chunks of 64, 8x4 microtile with k-paired f32x2
// (same engine as the attention S-GEMM). W tile transposed in smem so the
// k dimension is contiguous for ulonglong2 loads.
// grid = (128, 3), block = 256, dynamic smem = 52224 B (2 blocks/SM)
// ---------------------------------------------------------------------------
#define PROWP 68   // row pad: 272B rows, 16B aligned

__global__ void __launch_bounds__(256, 2) proj_kernel(
        const float* __restrict__ x,
        const float* __restrict__ Wq,
        const float* __restrict__ Wk,
        const float* __restrict__ Wv) {
    extern __shared__ float psm[];
    float (*sX)[PROWP]  = (float(*)[PROWP])psm;                  // [128 rows][64 k]
    float (*sWT)[PROWP] = (float(*)[PROWP])(psm + 128 * PROWP);  // [64 n][64 k]

    const int which = blockIdx.y;
    const float* W = (which == 0) ? Wq : ((which == 1) ? Wk : Wv);
    float* out = (which == 0) ? g_q : ((which == 1) ? g_k : g_v);

    const int rowBase = blockIdx.x * 128;
    const int tid = threadIdx.x;
    const int tx = tid & 15;
    const int ty = tid >> 4;

    u64t s2[8][4];   // (even-k, odd-k) partials
    #pragma unroll
    for (int i = 0; i < 8; i++)
        #pragma unroll
        for (int j = 0; j < 4; j++) s2[i][j] = 0ull;

    for (int k0 = 0; k0 < C_; k0 += 64) {
        // X tile: 128 rows x 64 k = 2048 float4, 8 per thread
        for (int i = tid; i < 128 * 16; i += 256) {
            int r = i >> 4, c4 = i & 15;
            *(float4*)&sX[r][c4 * 4] =
                *(const float4*)&x[(size_t)(rowBase + r) * C_ + k0 + c4 * 4];
        }
        // W tile transposed: gmem [64 k][64 n] -> sWT[n][k]
        for (int i = tid; i < 64 * 16; i += 256) {
            int r = i >> 4, c4 = i & 15;      // r = k index, c4 = n quad
            float4 v = *(const float4*)&W[(size_t)(k0 + r) * H_ + c4 * 4];
            sWT[c4 * 4 + 0][r] = v.x; sWT[c4 * 4 + 1][r] = v.y;
            sWT[c4 * 4 + 2][r] = v.z; sWT[c4 * 4 + 3][r] = v.w;
        }
        __syncthreads();

        #pragma unroll
        for (int kk = 0; kk < 64; kk += 4) {
            ulonglong2 kb[4];
            #pragma unroll
            for (int j = 0; j < 4; j++)
                kb[j] = *(const ulonglong2*)&sWT[tx + 16 * j][kk];
            #pragma unroll
            for (int i = 0; i < 8; i++) {
                ulonglong2 qa = *(const ulonglong2*)&sX[ty * 8 + i][kk];
                #pragma unroll
                for (int j = 0; j < 4; j++) {
                    s2[i][j] = ffma2(qa.x, kb[j].x, s2[i][j]);
                    s2[i][j] = ffma2(qa.y, kb[j].y, s2[i][j]);
                }
            }
        }
        __syncthreads();
    }

    // Collapse pairs and store (strided n = tx+16j; 2x64B segments per warp)
    #pragma unroll
    for (int i = 0; i < 8; i++) {
        #pragma unroll
        for (int j = 0; j < 4; j++) {
            float2 f = u2f(s2[i][j]);
            out[(size_t)(rowBase + ty * 8 + i) * H_ + tx + 16 * j] = f.x + f.y;
        }
    }
}

// ---------------------------------------------------------------------------
// Flash attention main pass (unchanged from R3: measured ~150us).
// q-tile = 128 rows, key-tile = 64; 8x4 microtile, k-paired f32x2;
// split-K halves + triangular pair balance. grid=(8,2,8).
// ---------------------------------------------------------------------------
#define QROWS 128
#define KKEYS 64
#define ROWP 68    // 68 % 32 == 4 banks/row; 272B rows -> 16B aligned
#define VROWP 66   // 66 % 32 == 2 banks/row; 264B rows -> 8B aligned

__global__ void __launch_bounds__(256, 1) attn_kernel() {
    extern __shared__ float sm[];
    float (*sQ)[ROWP]   = (float(*)[ROWP])sm;
    float (*sK)[ROWP]   = (float(*)[ROWP])(sm + QROWS * ROWP);
    float (*sVT)[VROWP] = (float(*)[VROWP])(sm + QROWS * ROWP + KKEYS * ROWP);
    float (*sP)[ROWP]   = (float(*)[ROWP])(sm + QROWS * ROWP + KKEYS * ROWP + H_ * VROWP);

    const int pair = blockIdx.x;   // 0..7
    const int hf   = blockIdx.y;   // 0..1  key-range half
    const int b    = blockIdx.z;   // batch
    const int tid  = threadIdx.x;
    const int tx   = tid & 15;
    const int ty   = tid >> 4;

    for (int side = 0; side < 2; side++) {
        const int qt = side ? (NQT128 - 1 - pair) : pair;

        // Load Q tile (128x64)
        const float* Qg = g_q + ((size_t)b * T_ + qt * QROWS) * H_;
        for (int i = tid; i < QROWS * (H_ / 4); i += 256) {
            int r = i >> 4, c4 = i & 15;
            *(float4*)&sQ[r][c4 * 4] = *(const float4*)&Qg[(size_t)r * H_ + c4 * 4];
        }

        u64t acc2[8][4];               // (even-k, odd-k) partial O sums
        float mrow[8], lrow[8];
        #pragma unroll
        for (int i = 0; i < 8; i++) {
            mrow[i] = -1e30f; lrow[i] = 0.0f;
            #pragma unroll
            for (int c = 0; c < 4; c++) acc2[i][c] = 0ull;
        }
        __syncthreads();

        const int kt0 = hf ? (qt + 1)     : 0;
        const int kt1 = hf ? (2 * qt + 2) : (qt + 1);
        for (int kt = kt0; kt < kt1; kt++) {
            // Load K tile [64 keys][64 h]
            const float* Kg = g_k + ((size_t)b * T_ + kt * KKEYS) * H_;
            for (int i = tid; i < KKEYS * (H_ / 4); i += 256) {
                int r = i >> 4, c4 = i & 15;
                *(float4*)&sK[r][c4 * 4] = *(const float4*)&Kg[(size_t)r * H_ + c4 * 4];
            }
            // Load V tile transposed: sVT[h][key]
            const float* Vg = g_v + ((size_t)b * T_ + kt * KKEYS) * H_;
            for (int i = tid; i < KKEYS * (H_ / 4); i += 256) {
                int r = i >> 4, c4 = i & 15;
                float4 v = *(const float4*)&Vg[(size_t)r * H_ + c4 * 4];
                sVT[c4 * 4 + 0][r] = v.x; sVT[c4 * 4 + 1][r] = v.y;
                sVT[c4 * 4 + 2][r] = v.z; sVT[c4 * 4 + 3][r] = v.w;
            }
            __syncthreads();

            // ---- S = Q K^T, k-paired f32x2 ----
            u64t s2[8][4];
            #pragma unroll
            for (int i = 0; i < 8; i++)
                #pragma unroll
                for (int j = 0; j < 4; j++) s2[i][j] = 0ull;

            #pragma unroll
            for (int kk = 0; kk < H_; kk += 4) {
                ulonglong2 kb[4];
                #pragma unroll
                for (int j = 0; j < 4; j++)
                    kb[j] = *(const ulonglong2*)&sK[tx + 16 * j][kk];
                #pragma unroll
                for (int i = 0; i < 8; i++) {
                    ulonglong2 qa = *(const ulonglong2*)&sQ[ty * 8 + i][kk];
                    #pragma unroll
                    for (int j = 0; j < 4; j++) {
                        s2[i][j] = ffma2(qa.x, kb[j].x, s2[i][j]);
                        s2[i][j] = ffma2(qa.y, kb[j].y, s2[i][j]);
                    }
                }
            }

            // ---- collapse pairs, causal mask, online softmax ----
            const bool diag = (kt >= 2 * qt);    // only last two tiles cross diagonal
            float s[8][4];
            #pragma unroll
            for (int i = 0; i < 8; i++) {
                const int row = qt * QROWS + ty * 8 + i;
                #pragma unroll
                for (int j = 0; j < 4; j++) {
                    float2 f = u2f(s2[i][j]);
                    s[i][j] = f.x + f.y;
                    if (diag) {
                        int key = kt * KKEYS + tx + 16 * j;
                        if (key > row) s[i][j] = -1e30f;
                    }
                }
            }
            #pragma unroll
            for (int i = 0; i < 8; i++) {
                float rmax = fmaxf(fmaxf(s[i][0], s[i][1]), fmaxf(s[i][2], s[i][3]));
                #pragma unroll
                for (int msk = 1; msk < 16; msk <<= 1)
                    rmax = fmaxf(rmax, __shfl_xor_sync(0xffffffffu, rmax, msk));
                float newm = fmaxf(mrow[i], rmax);
                float scale = __expf(mrow[i] - newm);
                float rsum = 0.0f;
                #pragma unroll
                for (int j = 0; j < 4; j++) {
                    float p = __expf(s[i][j] - newm);
                    s[i][j] = p;
                    rsum += p;
                }
                #pragma unroll
                for (int msk = 1; msk < 16; msk <<= 1)
                    rsum += __shfl_xor_sync(0xffffffffu, rsum, msk);
                lrow[i] = lrow[i] * scale + rsum;
                mrow[i] = newm;
                u64t sc2 = f2u(scale, scale);
                #pragma unroll
                for (int c = 0; c < 4; c++) acc2[i][c] = fmul2(acc2[i][c], sc2);
                #pragma unroll
                for (int j = 0; j < 4; j++) sP[ty * 8 + i][tx + 16 * j] = s[i][j];
            }
            __syncthreads();

            // ---- O += P @ V, k-paired f32x2 (P pairs contiguous, V transposed) ----
            #pragma unroll 2
            for (int kk = 0; kk < KKEYS; kk += 2) {
                u64t vb[4];
                #pragma unroll
                for (int c = 0; c < 4; c++)
                    vb[c] = *(const u64t*)&sVT[tx + 16 * c][kk];
                #pragma unroll
                for (int i = 0; i < 8; i++) {
                    u64t p2 = *(const u64t*)&sP[ty * 8 + i][kk];
                    #pragma unroll
                    for (int c = 0; c < 4; c++)
                        acc2[i][c] = ffma2(p2, vb[c], acc2[i][c]);
                }
            }
            __syncthreads();   // protect sK/sVT/sP before next tile's loads
        }

        // ---- write split-K partials (merge kernel normalizes) ----
        const int rowg = qt * QROWS + ty * 8;
        if (tx == 0) {
            #pragma unroll
            for (int i = 0; i < 8; i++) {
                g_pm[hf][b][rowg + i] = mrow[i];
                g_pl[hf][b][rowg + i] = lrow[i];
            }
        }
        #pragma unroll
        for (int i = 0; i < 8; i++) {
            #pragma unroll
            for (int c = 0; c < 4; c++) {
                float2 f = u2f(acc2[i][c]);
                g_po[hf][b][rowg + i][tx + 16 * c] = f.x + f.y;
            }
        }
    }
}

// ---------------------------------------------------------------------------
// Merge: out = (e0*O0 + e1*O1) / (e0*l0 + e1*l1), e_h = exp(m_h - max(m0,m1)).
// Fully-masked halves have m=-1e30 -> e underflows to exactly 0.
// ---------------------------------------------------------------------------
__global__ void merge_kernel(float* __restrict__ out) {
    int idx = blockIdx.x * 256 + threadIdx.x;   // 0 .. 16384*16-1
    int row = idx >> 4;
    int c4  = idx & 15;
    int b = row >> 11;
    int t = row & 2047;

    float m0 = g_pm[0][b][t], m1 = g_pm[1][b][t];
    float l0 = g_pl[0][b][t], l1 = g_pl[1][b][t];
    float M  = fmaxf(m0, m1);
    float e0 = __expf(m0 - M), e1 = __expf(m1 - M);
    float inv = 1.0f / (l0 * e0 + l1 * e1);

    float4 a0 = *(const float4*)&g_po[0][b][t][c4 * 4];
    float4 a1 = *(const float4*)&g_po[1][b][t][c4 * 4];
    float4 o;
    o.x = (a0.x * e0 + a1.x * e1) * inv;
    o.y = (a0.y * e0 + a1.y * e1) * inv;
    o.z = (a0.z * e0 + a1.z * e1) * inv;
    o.w = (a0.w * e0 + a1.w * e1) * inv;
    *(float4*)&out[(size_t)row * H_ + c4 * 4] = o;
}

// ---------------------------------------------------------------------------
// Harness entry. Inputs: x [B,T,C], Wq, Wk, Wv [C,H]. Output: [B,T,H] f32.
// ---------------------------------------------------------------------------
extern "C" void kernel_launch(void* const* d_in, const int* in_sizes, int n_in,
                              void* d_out, int out_size) {
    const float* x  = (const float*)d_in[0];
    const float* Wq = (const float*)d_in[1];
    const float* Wk = (const float*)d_in[2];
    const float* Wv = (const float*)d_in[3];
    float* out = (float*)d_out;
    (void)in_sizes; (void)n_in; (void)out_size;

    const int proj_smem = (128 * PROWP + 64 * PROWP) * (int)sizeof(float);   // 52224 B
    const int attn_smem =
        (QROWS * ROWP + KKEYS * ROWP + H_ * VROWP + QROWS * ROWP) * (int)sizeof(float); // 103936 B
    cudaFuncSetAttribute(proj_kernel, cudaFuncAttributeMaxDynamicSharedMemorySize,
                         proj_smem);
    cudaFuncSetAttribute(attn_kernel, cudaFuncAttributeMaxDynamicSharedMemorySize,
                         attn_smem);

    proj_kernel<<<dim3((B_ * T_) / 128, 3), 256, proj_smem>>>(x, Wq, Wk, Wv);
    attn_kernel<<<dim3(NPAIR, 2, B_), 256, attn_smem>>>();
    merge_kernel<<<(B_ * T_ * (H_ / 4)) / 256, 256>>>(out);
}

// round 8
// speedup vs baseline: 2.0456x; 1.3298x over previous
#include <cuda_runtime.h>
#include <cuda_bf16.h>
#include <cstdint>
#include <math.h>

#define B_ 8
#define T_ 2048
#define C_ 512
#define H_ 64
#define NQT128 (T_ / 128)     // 16 q-tiles of 128 rows
#define NPAIR (NQT128 / 2)    // 8 balanced pairs

// Scratch (device globals: no allocations allowed)
__device__ __align__(16) float g_q[B_ * T_ * H_];
__device__ __align__(16) float g_k[B_ * T_ * H_];
__device__ __align__(16) float g_v[B_ * T_ * H_];
// W split into bf16 hi/lo, transposed to [n][k] K-major (mma col-major operand)
__device__ __align__(16) __nv_bfloat16 g_whi[3][H_][C_];
__device__ __align__(16) __nv_bfloat16 g_wlo[3][H_][C_];
// split-K partials for attention
__device__ __align__(16) float g_pm[2][B_][T_];
__device__ __align__(16) float g_pl[2][B_][T_];
__device__ __align__(16) float g_po[2][B_][T_][H_];

// ---- packed f32x2 helpers ----
typedef unsigned long long u64t;
__device__ __forceinline__ u64t ffma2(u64t a, u64t b, u64t c) {
    u64t d; asm("fma.rn.f32x2 %0, %1, %2, %3;" : "=l"(d) : "l"(a), "l"(b), "l"(c));
    return d;
}
__device__ __forceinline__ u64t fmul2(u64t a, u64t b) {
    u64t d; asm("mul.rn.f32x2 %0, %1, %2;" : "=l"(d) : "l"(a), "l"(b));
    return d;
}
__device__ __forceinline__ float2 u2f(u64t v) {
    float2 f; asm("mov.b64 {%0, %1}, %2;" : "=f"(f.x), "=f"(f.y) : "l"(v));
    return f;
}
__device__ __forceinline__ u64t f2u(float x, float y) {
    u64t v; asm("mov.b64 %0, {%1, %2};" : "=l"(v) : "f"(x), "f"(y));
    return v;
}

// ---- mma.sync helpers ----
__device__ __forceinline__ void mma_bf16(float* d, const uint32_t* a, uint32_t b0,
                                         uint32_t b1) {
    asm volatile(
        "mma.sync.aligned.m16n8k16.row.col.f32.bf16.bf16.f32 "
        "{%0,%1,%2,%3}, {%4,%5,%6,%7}, {%8,%9}, {%0,%1,%2,%3};"
        : "+f"(d[0]), "+f"(d[1]), "+f"(d[2]), "+f"(d[3])
        : "r"(a[0]), "r"(a[1]), "r"(a[2]), "r"(a[3]), "r"(b0), "r"(b1));
}
__device__ __forceinline__ uint32_t packbf2(float a, float b) {
    __nv_bfloat162 t = __floats2bfloat162_rn(a, b);
    return *(uint32_t*)&t;
}

// ---------------------------------------------------------------------------
// prep_w: split W[C,H] fp32 into bf16 hi/lo, transposed to [o][n][k].
// ---------------------------------------------------------------------------
__global__ void prep_w_kernel(const float* __restrict__ Wq,
                              const float* __restrict__ Wk,
                              const float* __restrict__ Wv) {
    int idx = blockIdx.x * 256 + threadIdx.x;
    int o = idx >> 15;
    int n = (idx >> 9) & 63;
    int k = idx & 511;
    const float* W = (o == 0) ? Wq : ((o == 1) ? Wk : Wv);
    float v = W[(size_t)k * H_ + n];
    __nv_bfloat16 hi = __float2bfloat16(v);
    __nv_bfloat16 lo = __float2bfloat16(v - __bfloat162float(hi));
    g_whi[o][n][k] = hi;
    g_wlo[o][n][k] = lo;
}

// ---------------------------------------------------------------------------
// Projection v6: mma.sync bf16 3-term split GEMM, direct fragment loads.
// BUGFIX vs v5/v4: the B-tile smem copy previously iterated 6*256 with
// element stride q8*16 but copied only 8 bf16 per uint4 -> elements
// {8-15,24-31,40-47,56-63} of every row were stale (identical rel_err
// 1.074664 across two different fragment loaders pinned the bug to this
// shared loop). Now 6*512 iterations, q8&7, offset q8*8: full coverage.
// Fragment spec (m16n8k16, g = lane>>2, t = lane&3):
//   A row-major: a0=A[g][2t,2t+1] a1=A[g+8][..] a2=A[g][2t+8,..] a3=A[g+8][2t+8]
//   B col-major: b0=B[2t..2t+1][n=g]  b1=B[2t+8..][n=g]
//   C: c0,c1=D[g][2t..]; c2,c3=D[g+8][..]
// grid = 128, block = 256 (8 warps), dynamic smem = 92160 B
// ---------------------------------------------------------------------------
#define AP 72                    // padded k-extent (144B rows; conflict-free)
#define SM_AHI 0
#define SM_ALO (128 * AP * 2)                 // 18432
#define SM_BT  (2 * 128 * AP * 2)             // 36864; 6 tiles of 64*AP*2
#define BT_SZ  (64 * AP * 2)
#define PROJ_SMEM (SM_BT + 6 * BT_SZ)         // 92160

__global__ void __launch_bounds__(256, 1) proj_kernel(const float* __restrict__ x) {
    extern __shared__ __align__(16) char smem[];
    const int tid = threadIdx.x;
    const int wid = tid >> 5;
    const int lane = tid & 31;
    const int g = lane >> 2;      // fragment row/col group
    const int tq = lane & 3;      // thread-in-group
    const int rowBase = blockIdx.x * 128;

    float d[3][8][4];
    #pragma unroll
    for (int o = 0; o < 3; o++)
        #pragma unroll
        for (int nt = 0; nt < 8; nt++)
            #pragma unroll
            for (int r = 0; r < 4; r++) d[o][nt][r] = 0.0f;

    for (int c = 0; c < 8; c++) {
        // ---- build A tiles: x fp32 -> bf16 hi/lo ----
        for (int i = tid; i < 128 * 16; i += 256) {
            int r = i >> 4, q4 = i & 15;
            float4 v = *(const float4*)&x[(size_t)(rowBase + r) * C_ + c * 64 + q4 * 4];
            __nv_bfloat16 h0 = __float2bfloat16(v.x), h1 = __float2bfloat16(v.y);
            __nv_bfloat16 h2 = __float2bfloat16(v.z), h3 = __float2bfloat16(v.w);
            float l0 = v.x - __bfloat162float(h0), l1 = v.y - __bfloat162float(h1);
            float l2 = v.z - __bfloat162float(h2), l3 = v.w - __bfloat162float(h3);
            uint32_t off = (uint32_t)(r * AP + q4 * 4) * 2;
            __nv_bfloat162 hA; hA.x = h0; hA.y = h1;
            __nv_bfloat162 hB; hB.x = h2; hB.y = h3;
            *(uint2*)(smem + SM_AHI + off) = make_uint2(*(uint32_t*)&hA, *(uint32_t*)&hB);
            *(uint2*)(smem + SM_ALO + off) = make_uint2(packbf2(l0, l1), packbf2(l2, l3));
        }
        // ---- copy B tiles (bf16 [n][k]): 6 tiles x 64 rows x 8 uint4 (FULL rows) ----
        for (int i = tid; i < 6 * 512; i += 256) {
            int t = i >> 9, rem = i & 511;
            int n = rem >> 3, q8 = rem & 7;          // q8: 8 uint4 per 64-elem row
            int o = (t >= 3) ? (t - 3) : t;
            const __nv_bfloat16* src = (t >= 3) ? &g_wlo[o][n][c * 64 + q8 * 8]
                                                : &g_whi[o][n][c * 64 + q8 * 8];
            *(uint4*)(smem + SM_BT + t * BT_SZ + (uint32_t)(n * AP + q8 * 8) * 2) =
                *(const uint4*)src;
        }
        __syncthreads();

        // ---- A fragments: direct loads per spec ----
        uint32_t aHi[4][4], aLo[4][4];
        {
            const int r0 = wid * 16 + g;
            #pragma unroll
            for (int ks = 0; ks < 4; ks++) {
                const int k0 = ks * 16 + tq * 2;
                uint32_t o00 = (uint32_t)(r0 * AP + k0) * 2;         // row g,   k
                uint32_t o10 = (uint32_t)((r0 + 8) * AP + k0) * 2;   // row g+8, k
                aHi[ks][0] = *(const uint32_t*)(smem + SM_AHI + o00);
                aHi[ks][1] = *(const uint32_t*)(smem + SM_AHI + o10);
                aHi[ks][2] = *(const uint32_t*)(smem + SM_AHI + o00 + 16);  // k+8
                aHi[ks][3] = *(const uint32_t*)(smem + SM_AHI + o10 + 16);
                aLo[ks][0] = *(const uint32_t*)(smem + SM_ALO + o00);
                aLo[ks][1] = *(const uint32_t*)(smem + SM_ALO + o10);
                aLo[ks][2] = *(const uint32_t*)(smem + SM_ALO + o00 + 16);
                aLo[ks][3] = *(const uint32_t*)(smem + SM_ALO + o10 + 16);
            }
        }

        // ---- MMA: per (o, ks): B-hi pass (hi*hi + lo*hi), then B-lo pass ----
        #pragma unroll
        for (int o = 0; o < 3; o++) {
            const char* bHi = smem + SM_BT + o * BT_SZ;
            const char* bLo = smem + SM_BT + (o + 3) * BT_SZ;
            #pragma unroll
            for (int ks = 0; ks < 4; ks++) {
                const int k0 = ks * 16 + tq * 2;
                uint32_t bf[8][2];
                #pragma unroll
                for (int nt = 0; nt < 8; nt++) {
                    uint32_t ob = (uint32_t)((nt * 8 + g) * AP + k0) * 2;
                    bf[nt][0] = *(const uint32_t*)(bHi + ob);        // k pair
                    bf[nt][1] = *(const uint32_t*)(bHi + ob + 16);   // k+8 pair
                }
                #pragma unroll
                for (int nt = 0; nt < 8; nt++) {
                    mma_bf16(d[o][nt], aHi[ks], bf[nt][0], bf[nt][1]);  // hi*hi
                    mma_bf16(d[o][nt], aLo[ks], bf[nt][0], bf[nt][1]);  // lo*hi
                }
                #pragma unroll
                for (int nt = 0; nt < 8; nt++) {
                    uint32_t ob = (uint32_t)((nt * 8 + g) * AP + k0) * 2;
                    bf[nt][0] = *(const uint32_t*)(bLo + ob);
                    bf[nt][1] = *(const uint32_t*)(bLo + ob + 16);
                }
                #pragma unroll
                for (int nt = 0; nt < 8; nt++)
                    mma_bf16(d[o][nt], aHi[ks], bf[nt][0], bf[nt][1]);  // hi*lo
            }
        }
        __syncthreads();   // tiles rewritten next chunk
    }

    // ---- epilogue: C frag -> gmem fp32 ----
    #pragma unroll
    for (int o = 0; o < 3; o++) {
        float* dst = (o == 0) ? g_q : ((o == 1) ? g_k : g_v);
        size_t r0 = (size_t)(rowBase + wid * 16 + g);
        #pragma unroll
        for (int nt = 0; nt < 8; nt++) {
            int col = nt * 8 + tq * 2;
            *(float2*)&dst[r0 * H_ + col]       = make_float2(d[o][nt][0], d[o][nt][1]);
            *(float2*)&dst[(r0 + 8) * H_ + col] = make_float2(d[o][nt][2], d[o][nt][3]);
        }
    }
}

// ---------------------------------------------------------------------------
// Flash attention main pass (unchanged; ~150us measured).
// ---------------------------------------------------------------------------
#define QROWS 128
#define KKEYS 64
#define ROWP 68
#define VROWP 66

__global__ void __launch_bounds__(256, 1) attn_kernel() {
    extern __shared__ float sm[];
    float (*sQ)[ROWP]   = (float(*)[ROWP])sm;
    float (*sK)[ROWP]   = (float(*)[ROWP])(sm + QROWS * ROWP);
    float (*sVT)[VROWP] = (float(*)[VROWP])(sm + QROWS * ROWP + KKEYS * ROWP);
    float (*sP)[ROWP]   = (float(*)[ROWP])(sm + QROWS * ROWP + KKEYS * ROWP + H_ * VROWP);

    const int pair = blockIdx.x;
    const int hf   = blockIdx.y;
    const int b    = blockIdx.z;
    const int tid  = threadIdx.x;
    const int tx   = tid & 15;
    const int ty   = tid >> 4;

    for (int side = 0; side < 2; side++) {
        const int qt = side ? (NQT128 - 1 - pair) : pair;

        const float* Qg = g_q + ((size_t)b * T_ + qt * QROWS) * H_;
        for (int i = tid; i < QROWS * (H_ / 4); i += 256) {
            int r = i >> 4, c4 = i & 15;
            *(float4*)&sQ[r][c4 * 4] = *(const float4*)&Qg[(size_t)r * H_ + c4 * 4];
        }

        u64t acc2[8][4];
        float mrow[8], lrow[8];
        #pragma unroll
        for (int i = 0; i < 8; i++) {
            mrow[i] = -1e30f; lrow[i] = 0.0f;
            #pragma unroll
            for (int c = 0; c < 4; c++) acc2[i][c] = 0ull;
        }
        __syncthreads();

        const int kt0 = hf ? (qt + 1)     : 0;
        const int kt1 = hf ? (2 * qt + 2) : (qt + 1);
        for (int kt = kt0; kt < kt1; kt++) {
            const float* Kg = g_k + ((size_t)b * T_ + kt * KKEYS) * H_;
            for (int i = tid; i < KKEYS * (H_ / 4); i += 256) {
                int r = i >> 4, c4 = i & 15;
                *(float4*)&sK[r][c4 * 4] = *(const float4*)&Kg[(size_t)r * H_ + c4 * 4];
            }
            const float* Vg = g_v + ((size_t)b * T_ + kt * KKEYS) * H_;
            for (int i = tid; i < KKEYS * (H_ / 4); i += 256) {
                int r = i >> 4, c4 = i & 15;
                float4 v = *(const float4*)&Vg[(size_t)r * H_ + c4 * 4];
                sVT[c4 * 4 + 0][r] = v.x; sVT[c4 * 4 + 1][r] = v.y;
                sVT[c4 * 4 + 2][r] = v.z; sVT[c4 * 4 + 3][r] = v.w;
            }
            __syncthreads();

            u64t s2[8][4];
            #pragma unroll
            for (int i = 0; i < 8; i++)
                #pragma unroll
                for (int j = 0; j < 4; j++) s2[i][j] = 0ull;

            #pragma unroll
            for (int kk = 0; kk < H_; kk += 4) {
                ulonglong2 kb[4];
                #pragma unroll
                for (int j = 0; j < 4; j++)
                    kb[j] = *(const ulonglong2*)&sK[tx + 16 * j][kk];
                #pragma unroll
                for (int i = 0; i < 8; i++) {
                    ulonglong2 qa = *(const ulonglong2*)&sQ[ty * 8 + i][kk];
                    #pragma unroll
                    for (int j = 0; j < 4; j++) {
                        s2[i][j] = ffma2(qa.x, kb[j].x, s2[i][j]);
                        s2[i][j] = ffma2(qa.y, kb[j].y, s2[i][j]);
                    }
                }
            }

            const bool diag = (kt >= 2 * qt);
            float s[8][4];
            #pragma unroll
            for (int i = 0; i < 8; i++) {
                const int row = qt * QROWS + ty * 8 + i;
                #pragma unroll
                for (int j = 0; j < 4; j++) {
                    float2 f = u2f(s2[i][j]);
                    s[i][j] = f.x + f.y;
                    if (diag) {
                        int key = kt * KKEYS + tx + 16 * j;
                        if (key > row) s[i][j] = -1e30f;
                    }
                }
            }
            #pragma unroll
            for (int i = 0; i < 8; i++) {
                float rmax = fmaxf(fmaxf(s[i][0], s[i][1]), fmaxf(s[i][2], s[i][3]));
                #pragma unroll
                for (int msk = 1; msk < 16; msk <<= 1)
                    rmax = fmaxf(rmax, __shfl_xor_sync(0xffffffffu, rmax, msk));
                float newm = fmaxf(mrow[i], rmax);
                float scale = __expf(mrow[i] - newm);
                float rsum = 0.0f;
                #pragma unroll
                for (int j = 0; j < 4; j++) {
                    float p = __expf(s[i][j] - newm);
                    s[i][j] = p;
                    rsum += p;
                }
                #pragma unroll
                for (int msk = 1; msk < 16; msk <<= 1)
                    rsum += __shfl_xor_sync(0xffffffffu, rsum, msk);
                lrow[i] = lrow[i] * scale + rsum;
                mrow[i] = newm;
                u64t sc2 = f2u(scale, scale);
                #pragma unroll
                for (int c = 0; c < 4; c++) acc2[i][c] = fmul2(acc2[i][c], sc2);
                #pragma unroll
                for (int j = 0; j < 4; j++) sP[ty * 8 + i][tx + 16 * j] = s[i][j];
            }
            __syncthreads();

            #pragma unroll 2
            for (int kk = 0; kk < KKEYS; kk += 2) {
                u64t vb[4];
                #pragma unroll
                for (int c = 0; c < 4; c++)
                    vb[c] = *(const u64t*)&sVT[tx + 16 * c][kk];
                #pragma unroll
                for (int i = 0; i < 8; i++) {
                    u64t p2 = *(const u64t*)&sP[ty * 8 + i][kk];
                    #pragma unroll
                    for (int c = 0; c < 4; c++)
                        acc2[i][c] = ffma2(p2, vb[c], acc2[i][c]);
                }
            }
            __syncthreads();
        }

        const int rowg = qt * QROWS + ty * 8;
        if (tx == 0) {
            #pragma unroll
            for (int i = 0; i < 8; i++) {
                g_pm[hf][b][rowg + i] = mrow[i];
                g_pl[hf][b][rowg + i] = lrow[i];
            }
        }
        #pragma unroll
        for (int i = 0; i < 8; i++) {
            #pragma unroll
            for (int c = 0; c < 4; c++) {
                float2 f = u2f(acc2[i][c]);
                g_po[hf][b][rowg + i][tx + 16 * c] = f.x + f.y;
            }
        }
    }
}

// ---------------------------------------------------------------------------
// Merge split-K halves.
// ---------------------------------------------------------------------------
__global__ void merge_kernel(float* __restrict__ out) {
    int idx = blockIdx.x * 256 + threadIdx.x;
    int row = idx >> 4;
    int c4  = idx & 15;
    int b = row >> 11;
    int t = row & 2047;

    float m0 = g_pm[0][b][t], m1 = g_pm[1][b][t];
    float l0 = g_pl[0][b][t], l1 = g_pl[1][b][t];
    float M  = fmaxf(m0, m1);
    float e0 = __expf(m0 - M), e1 = __expf(m1 - M);
    float inv = 1.0f / (l0 * e0 + l1 * e1);

    float4 a0 = *(const float4*)&g_po[0][b][t][c4 * 4];
    float4 a1 = *(const float4*)&g_po[1][b][t][c4 * 4];
    float4 o;
    o.x = (a0.x * e0 + a1.x * e1) * inv;
    o.y = (a0.y * e0 + a1.y * e1) * inv;
    o.z = (a0.z * e0 + a1.z * e1) * inv;
    o.w = (a0.w * e0 + a1.w * e1) * inv;
    *(float4*)&out[(size_t)row * H_ + c4 * 4] = o;
}

// ---------------------------------------------------------------------------
// Harness entry. Inputs: x [B,T,C], Wq, Wk, Wv [C,H]. Output: [B,T,H] f32.
// ---------------------------------------------------------------------------
extern "C" void kernel_launch(void* const* d_in, const int* in_sizes, int n_in,
                              void* d_out, int out_size) {
    const float* x  = (const float*)d_in[0];
    const float* Wq = (const float*)d_in[1];
    const float* Wk = (const float*)d_in[2];
    const float* Wv = (const float*)d_in[3];
    float* out = (float*)d_out;
    (void)in_sizes; (void)n_in; (void)out_size;

    const int attn_smem =
        (QROWS * ROWP + KKEYS * ROWP + H_ * VROWP + QROWS * ROWP) * (int)sizeof(float);
    cudaFuncSetAttribute(proj_kernel, cudaFuncAttributeMaxDynamicSharedMemorySize,
                         PROJ_SMEM);
    cudaFuncSetAttribute(attn_kernel, cudaFuncAttributeMaxDynamicSharedMemorySize,
                         attn_smem);

    prep_w_kernel<<<384, 256>>>(Wq, Wk, Wv);
    proj_kernel<<<128, 256, PROJ_SMEM>>>(x);
    attn_kernel<<<dim3(NPAIR, 2, B_), 256, attn_smem>>>();
    merge_kernel<<<(B_ * T_ * (H_ / 4)) / 256, 256>>>(out);
}

// round 9
// speedup vs baseline: 2.8260x; 1.3815x over previous
#include <cuda_runtime.h>
#include <cuda_bf16.h>
#include <cstdint>
#include <math.h>

#define B_ 8
#define T_ 2048
#define C_ 512
#define H_ 64
#define NQT128 (T_ / 128)     // 16 q-tiles of 128 rows
#define NPAIR (NQT128 / 2)    // 8 balanced pairs

// ---- device scratch (no allocations allowed) ----
// W split bf16 hi/lo, [o][n][k]
__device__ __align__(16) __nv_bfloat16 g_whi[3][H_][C_];
__device__ __align__(16) __nv_bfloat16 g_wlo[3][H_][C_];
// projections, bf16 hi/lo. Q,K row-major [tok][h]; V transposed [h][tok].
__device__ __align__(16) __nv_bfloat16 g_qhi[B_ * T_][H_];
__device__ __align__(16) __nv_bfloat16 g_qlo[B_ * T_][H_];
__device__ __align__(16) __nv_bfloat16 g_khi[B_ * T_][H_];
__device__ __align__(16) __nv_bfloat16 g_klo[B_ * T_][H_];
__device__ __align__(16) __nv_bfloat16 g_vthi[H_][B_ * T_];
__device__ __align__(16) __nv_bfloat16 g_vtlo[H_][B_ * T_];
// split-K partials
__device__ __align__(16) float g_pm[2][B_][T_];
__device__ __align__(16) float g_pl[2][B_][T_];
__device__ __align__(16) float g_po[2][B_][T_][H_];

// ---- mma.sync helper (fragment mapping validated in R8 proj) ----
__device__ __forceinline__ void mma_bf16(float* d, const uint32_t* a, uint32_t b0,
                                         uint32_t b1) {
    asm volatile(
        "mma.sync.aligned.m16n8k16.row.col.f32.bf16.bf16.f32 "
        "{%0,%1,%2,%3}, {%4,%5,%6,%7}, {%8,%9}, {%0,%1,%2,%3};"
        : "+f"(d[0]), "+f"(d[1]), "+f"(d[2]), "+f"(d[3])
        : "r"(a[0]), "r"(a[1]), "r"(a[2]), "r"(a[3]), "r"(b0), "r"(b1));
}
__device__ __forceinline__ uint32_t packbf2(float a, float b) {
    __nv_bfloat162 t = __floats2bfloat162_rn(a, b);
    return *(uint32_t*)&t;
}

// ---------------------------------------------------------------------------
// prep_w: split W[C,H] fp32 into bf16 hi/lo, transposed to [o][n][k].
// ---------------------------------------------------------------------------
__global__ void prep_w_kernel(const float* __restrict__ Wq,
                              const float* __restrict__ Wk,
                              const float* __restrict__ Wv) {
    int idx = blockIdx.x * 256 + threadIdx.x;
    int o = idx >> 15;
    int n = (idx >> 9) & 63;
    int k = idx & 511;
    const float* W = (o == 0) ? Wq : ((o == 1) ? Wk : Wv);
    float v = W[(size_t)k * H_ + n];
    __nv_bfloat16 hi = __float2bfloat16(v);
    __nv_bfloat16 lo = __float2bfloat16(v - __bfloat162float(hi));
    g_whi[o][n][k] = hi;
    g_wlo[o][n][k] = lo;
}

// ---------------------------------------------------------------------------
// Projection (R8-validated mma engine). Epilogue now writes bf16 hi/lo:
// Q,K row-major packed u32 pairs; V transposed per-element.
// grid = 128, block = 256 (8 warps), dynamic smem = 92160 B
// ---------------------------------------------------------------------------
#define AP 72
#define SM_AHI 0
#define SM_ALO (128 * AP * 2)
#define SM_BT  (2 * 128 * AP * 2)
#define BT_SZ  (64 * AP * 2)
#define PROJ_SMEM (SM_BT + 6 * BT_SZ)

__global__ void __launch_bounds__(256, 1) proj_kernel(const float* __restrict__ x) {
    extern __shared__ __align__(16) char smem[];
    const int tid = threadIdx.x;
    const int wid = tid >> 5;
    const int lane = tid & 31;
    const int g = lane >> 2;
    const int tq = lane & 3;
    const int rowBase = blockIdx.x * 128;

    float d[3][8][4];
    #pragma unroll
    for (int o = 0; o < 3; o++)
        #pragma unroll
        for (int nt = 0; nt < 8; nt++)
            #pragma unroll
            for (int r = 0; r < 4; r++) d[o][nt][r] = 0.0f;

    for (int c = 0; c < 8; c++) {
        for (int i = tid; i < 128 * 16; i += 256) {
            int r = i >> 4, q4 = i & 15;
            float4 v = *(const float4*)&x[(size_t)(rowBase + r) * C_ + c * 64 + q4 * 4];
            __nv_bfloat16 h0 = __float2bfloat16(v.x), h1 = __float2bfloat16(v.y);
            __nv_bfloat16 h2 = __float2bfloat16(v.z), h3 = __float2bfloat16(v.w);
            float l0 = v.x - __bfloat162float(h0), l1 = v.y - __bfloat162float(h1);
            float l2 = v.z - __bfloat162float(h2), l3 = v.w - __bfloat162float(h3);
            uint32_t off = (uint32_t)(r * AP + q4 * 4) * 2;
            __nv_bfloat162 hA; hA.x = h0; hA.y = h1;
            __nv_bfloat162 hB; hB.x = h2; hB.y = h3;
            *(uint2*)(smem + SM_AHI + off) = make_uint2(*(uint32_t*)&hA, *(uint32_t*)&hB);
            *(uint2*)(smem + SM_ALO + off) = make_uint2(packbf2(l0, l1), packbf2(l2, l3));
        }
        for (int i = tid; i < 6 * 512; i += 256) {
            int t = i >> 9, rem = i & 511;
            int n = rem >> 3, q8 = rem & 7;
            int o = (t >= 3) ? (t - 3) : t;
            const __nv_bfloat16* src = (t >= 3) ? &g_wlo[o][n][c * 64 + q8 * 8]
                                                : &g_whi[o][n][c * 64 + q8 * 8];
            *(uint4*)(smem + SM_BT + t * BT_SZ + (uint32_t)(n * AP + q8 * 8) * 2) =
                *(const uint4*)src;
        }
        __syncthreads();

        uint32_t aHi[4][4], aLo[4][4];
        {
            const int r0 = wid * 16 + g;
            #pragma unroll
            for (int ks = 0; ks < 4; ks++) {
                const int k0 = ks * 16 + tq * 2;
                uint32_t o00 = (uint32_t)(r0 * AP + k0) * 2;
                uint32_t o10 = (uint32_t)((r0 + 8) * AP + k0) * 2;
                aHi[ks][0] = *(const uint32_t*)(smem + SM_AHI + o00);
                aHi[ks][1] = *(const uint32_t*)(smem + SM_AHI + o10);
                aHi[ks][2] = *(const uint32_t*)(smem + SM_AHI + o00 + 16);
                aHi[ks][3] = *(const uint32_t*)(smem + SM_AHI + o10 + 16);
                aLo[ks][0] = *(const uint32_t*)(smem + SM_ALO + o00);
                aLo[ks][1] = *(const uint32_t*)(smem + SM_ALO + o10);
                aLo[ks][2] = *(const uint32_t*)(smem + SM_ALO + o00 + 16);
                aLo[ks][3] = *(const uint32_t*)(smem + SM_ALO + o10 + 16);
            }
        }

        #pragma unroll
        for (int o = 0; o < 3; o++) {
            const char* bHi = smem + SM_BT + o * BT_SZ;
            const char* bLo = smem + SM_BT + (o + 3) * BT_SZ;
            #pragma unroll
            for (int ks = 0; ks < 4; ks++) {
                const int k0 = ks * 16 + tq * 2;
                uint32_t bf[8][2];
                #pragma unroll
                for (int nt = 0; nt < 8; nt++) {
                    uint32_t ob = (uint32_t)((nt * 8 + g) * AP + k0) * 2;
                    bf[nt][0] = *(const uint32_t*)(bHi + ob);
                    bf[nt][1] = *(const uint32_t*)(bHi + ob + 16);
                }
                #pragma unroll
                for (int nt = 0; nt < 8; nt++) {
                    mma_bf16(d[o][nt], aHi[ks], bf[nt][0], bf[nt][1]);
                    mma_bf16(d[o][nt], aLo[ks], bf[nt][0], bf[nt][1]);
                }
                #pragma unroll
                for (int nt = 0; nt < 8; nt++) {
                    uint32_t ob = (uint32_t)((nt * 8 + g) * AP + k0) * 2;
                    bf[nt][0] = *(const uint32_t*)(bLo + ob);
                    bf[nt][1] = *(const uint32_t*)(bLo + ob + 16);
                }
                #pragma unroll
                for (int nt = 0; nt < 8; nt++)
                    mma_bf16(d[o][nt], aHi[ks], bf[nt][0], bf[nt][1]);
            }
        }
        __syncthreads();
    }

    // ---- epilogue: bf16 hi/lo outputs ----
    const size_t r0 = (size_t)(rowBase + wid * 16 + g);
    #pragma unroll
    for (int o = 0; o < 2; o++) {             // Q, K: [tok][h] packed u32
        __nv_bfloat16 (*dsthi)[H_] = o ? g_khi : g_qhi;
        __nv_bfloat16 (*dstlo)[H_] = o ? g_klo : g_qlo;
        #pragma unroll
        for (int nt = 0; nt < 8; nt++) {
            int col = nt * 8 + tq * 2;
            #pragma unroll
            for (int h = 0; h < 2; h++) {     // h=0: row g, h=1: row g+8
                float v0 = d[o][nt][h * 2], v1 = d[o][nt][h * 2 + 1];
                __nv_bfloat16 h0 = __float2bfloat16(v0), h1 = __float2bfloat16(v1);
                float l0 = v0 - __bfloat162float(h0), l1 = v1 - __bfloat162float(h1);
                __nv_bfloat162 hp; hp.x = h0; hp.y = h1;
                *(uint32_t*)&dsthi[r0 + h * 8][col] = *(uint32_t*)&hp;
                *(uint32_t*)&dstlo[r0 + h * 8][col] = packbf2(l0, l1);
            }
        }
    }
    #pragma unroll
    for (int nt = 0; nt < 8; nt++) {          // V: transposed [h][tok]
        #pragma unroll
        for (int j = 0; j < 4; j++) {
            int col = nt * 8 + tq * 2 + (j & 1);
            size_t tok = r0 + (j >> 1) * 8;
            float v = d[2][nt][j];
            __nv_bfloat16 hi = __float2bfloat16(v);
            g_vthi[col][tok] = hi;
            g_vtlo[col][tok] = __float2bfloat16(v - __bfloat162float(hi));
        }
    }
}

// ---------------------------------------------------------------------------
// Flash attention, mma.sync edition.
// 128-row q-tiles x 64-key tiles; 8 warps x 16 rows; split-K + pair balance.
// S = 3-term bf16 split (qhi*khi + qlo*khi + qhi*klo), err ~1e-5.
// PV = bf16 P (single term; l summed from ROUNDED p -> normalization cancels
// rounding) x V hi/lo (2 terms).
// smem: sKhi|sKlo|sVhi|sVlo [64][72] bf16 + sP [128][72] bf16 = 55296 B.
// grid=(8,2,8), block=256.
// ---------------------------------------------------------------------------
#define APB 72
#define ROWB (APB * 2)          // 144 B row stride
#define SK_HI 0
#define SK_LO 9216
#define SV_HI 18432
#define SV_LO 27648
#define SP_OFF 36864
#define ATTN_SMEM (SP_OFF + 128 * ROWB)   // 55296

__global__ void __launch_bounds__(256, 1) attn_kernel() {
    extern __shared__ __align__(16) char sm[];
    const int pair = blockIdx.x;
    const int hf   = blockIdx.y;
    const int b    = blockIdx.z;
    const int tid  = threadIdx.x;
    const int wid  = tid >> 5;
    const int lane = tid & 31;
    const int g    = lane >> 2;
    const int tq   = lane & 3;

    for (int side = 0; side < 2; side++) {
        const int qt = side ? (NQT128 - 1 - pair) : pair;
        const int row0 = qt * 128 + wid * 16 + g;   // within batch
        const int row1 = row0 + 8;
        const size_t tok0 = (size_t)b * T_ + row0;

        // ---- Q fragments straight from gmem (once per q-tile) ----
        uint32_t qhi[4][4], qlo[4][4];
        #pragma unroll
        for (int ks = 0; ks < 4; ks++) {
            const int k0 = ks * 16 + tq * 2;
            qhi[ks][0] = *(const uint32_t*)&g_qhi[tok0][k0];
            qhi[ks][1] = *(const uint32_t*)&g_qhi[tok0 + 8][k0];
            qhi[ks][2] = *(const uint32_t*)&g_qhi[tok0][k0 + 8];
            qhi[ks][3] = *(const uint32_t*)&g_qhi[tok0 + 8][k0 + 8];
            qlo[ks][0] = *(const uint32_t*)&g_qlo[tok0][k0];
            qlo[ks][1] = *(const uint32_t*)&g_qlo[tok0 + 8][k0];
            qlo[ks][2] = *(const uint32_t*)&g_qlo[tok0][k0 + 8];
            qlo[ks][3] = *(const uint32_t*)&g_qlo[tok0 + 8][k0 + 8];
        }

        float O[8][4];
        #pragma unroll
        for (int nt = 0; nt < 8; nt++)
            #pragma unroll
            for (int r = 0; r < 4; r++) O[nt][r] = 0.0f;
        float m0 = -1e30f, m1 = -1e30f, l0 = 0.0f, l1 = 0.0f;

        const int kt0 = hf ? (qt + 1)     : 0;
        const int kt1 = hf ? (2 * qt + 2) : (qt + 1);
        for (int kt = kt0; kt < kt1; kt++) {
            // ---- fill K/V tiles (bf16 hi/lo, straight uint4 copies) ----
            for (int i = tid; i < 4 * 512; i += 256) {
                int which = i >> 9, rem = i & 511;
                int r = rem >> 3, q8 = rem & 7;
                const __nv_bfloat16* src;
                if      (which == 0) src = &g_khi[(size_t)b * T_ + kt * 64 + r][q8 * 8];
                else if (which == 1) src = &g_klo[(size_t)b * T_ + kt * 64 + r][q8 * 8];
                else if (which == 2) src = &g_vthi[r][(size_t)b * T_ + kt * 64 + q8 * 8];
                else                 src = &g_vtlo[r][(size_t)b * T_ + kt * 64 + q8 * 8];
                *(uint4*)(sm + which * 9216 + r * ROWB + q8 * 16) = *(const uint4*)src;
            }
            __syncthreads();

            // ---- S = Q K^T, 3-term split ----
            float s[8][4];
            #pragma unroll
            for (int nt = 0; nt < 8; nt++)
                #pragma unroll
                for (int r = 0; r < 4; r++) s[nt][r] = 0.0f;
            #pragma unroll
            for (int ks = 0; ks < 4; ks++) {
                const int kb = (ks * 16 + tq * 2) * 2;
                #pragma unroll
                for (int nt = 0; nt < 8; nt++) {
                    const char* rh = sm + SK_HI + (nt * 8 + g) * ROWB;
                    uint32_t b0 = *(const uint32_t*)(rh + kb);
                    uint32_t b1 = *(const uint32_t*)(rh + kb + 16);
                    mma_bf16(s[nt], qhi[ks], b0, b1);
                    mma_bf16(s[nt], qlo[ks], b0, b1);
                    const char* rl = sm + SK_LO + (nt * 8 + g) * ROWB;
                    uint32_t c0 = *(const uint32_t*)(rl + kb);
                    uint32_t c1 = *(const uint32_t*)(rl + kb + 16);
                    mma_bf16(s[nt], qhi[ks], c0, c1);
                }
            }

            // ---- causal mask on diagonal-crossing tiles ----
            if (kt >= 2 * qt) {
                #pragma unroll
                for (int nt = 0; nt < 8; nt++) {
                    int col = kt * 64 + nt * 8 + tq * 2;
                    if (col > row0)     s[nt][0] = -1e30f;
                    if (col + 1 > row0) s[nt][1] = -1e30f;
                    if (col > row1)     s[nt][2] = -1e30f;
                    if (col + 1 > row1) s[nt][3] = -1e30f;
                }
            }

            // ---- online softmax on fragments ----
            float a0 = -1e30f, a1 = -1e30f;
            #pragma unroll
            for (int nt = 0; nt < 8; nt++) {
                a0 = fmaxf(a0, fmaxf(s[nt][0], s[nt][1]));
                a1 = fmaxf(a1, fmaxf(s[nt][2], s[nt][3]));
            }
            a0 = fmaxf(a0, __shfl_xor_sync(0xffffffffu, a0, 1));
            a0 = fmaxf(a0, __shfl_xor_sync(0xffffffffu, a0, 2));
            a1 = fmaxf(a1, __shfl_xor_sync(0xffffffffu, a1, 1));
            a1 = fmaxf(a1, __shfl_xor_sync(0xffffffffu, a1, 2));
            float nm0 = fmaxf(m0, a0), nm1 = fmaxf(m1, a1);
            float sc0 = __expf(m0 - nm0), sc1 = __expf(m1 - nm1);
            float rs0 = 0.0f, rs1 = 0.0f;
            char* prow0 = sm + SP_OFF + (wid * 16 + g) * ROWB;
            #pragma unroll
            for (int nt = 0; nt < 8; nt++) {
                float p00 = __expf(s[nt][0] - nm0), p01 = __expf(s[nt][1] - nm0);
                float p10 = __expf(s[nt][2] - nm1), p11 = __expf(s[nt][3] - nm1);
                __nv_bfloat162 r0p = __floats2bfloat162_rn(p00, p01);
                __nv_bfloat162 r1p = __floats2bfloat162_rn(p10, p11);
                rs0 += __bfloat162float(r0p.x) + __bfloat162float(r0p.y);
                rs1 += __bfloat162float(r1p.x) + __bfloat162float(r1p.y);
                *(uint32_t*)(prow0 + (nt * 8 + tq * 2) * 2) = *(uint32_t*)&r0p;
                *(uint32_t*)(prow0 + 8 * ROWB + (nt * 8 + tq * 2) * 2) = *(uint32_t*)&r1p;
            }
            rs0 += __shfl_xor_sync(0xffffffffu, rs0, 1);
            rs0 += __shfl_xor_sync(0xffffffffu, rs0, 2);
            rs1 += __shfl_xor_sync(0xffffffffu, rs1, 1);
            rs1 += __shfl_xor_sync(0xffffffffu, rs1, 2);
            l0 = l0 * sc0 + rs0; m0 = nm0;
            l1 = l1 * sc1 + rs1; m1 = nm1;
            #pragma unroll
            for (int nt = 0; nt < 8; nt++) {
                O[nt][0] *= sc0; O[nt][1] *= sc0;
                O[nt][2] *= sc1; O[nt][3] *= sc1;
            }
            __syncwarp();   // sP rows are warp-local: warp-order suffices

            // ---- O += P @ V (V hi + V lo) ----
            #pragma unroll
            for (int ks = 0; ks < 4; ks++) {
                const int kb = (ks * 16 + tq * 2) * 2;
                uint32_t pa[4];
                const char* pr = sm + SP_OFF + (wid * 16 + g) * ROWB;
                pa[0] = *(const uint32_t*)(pr + kb);
                pa[1] = *(const uint32_t*)(pr + 8 * ROWB + kb);
                pa[2] = *(const uint32_t*)(pr + kb + 16);
                pa[3] = *(const uint32_t*)(pr + 8 * ROWB + kb + 16);
                #pragma unroll
                for (int nt = 0; nt < 8; nt++) {
                    const char* vh = sm + SV_HI + (nt * 8 + g) * ROWB;
                    uint32_t b0 = *(const uint32_t*)(vh + kb);
                    uint32_t b1 = *(const uint32_t*)(vh + kb + 16);
                    mma_bf16(O[nt], pa, b0, b1);
                    const char* vl = sm + SV_LO + (nt * 8 + g) * ROWB;
                    b0 = *(const uint32_t*)(vl + kb);
                    b1 = *(const uint32_t*)(vl + kb + 16);
                    mma_bf16(O[nt], pa, b0, b1);
                }
            }
            __syncthreads();   // sK/sV (all warps) + sP reuse next tile
        }

        // ---- write split-K partials ----
        if (tq == 0) {
            g_pm[hf][b][row0] = m0; g_pl[hf][b][row0] = l0;
            g_pm[hf][b][row1] = m1; g_pl[hf][b][row1] = l1;
        }
        #pragma unroll
        for (int nt = 0; nt < 8; nt++) {
            int col = nt * 8 + tq * 2;
            *(float2*)&g_po[hf][b][row0][col] = make_float2(O[nt][0], O[nt][1]);
            *(float2*)&g_po[hf][b][row1][col] = make_float2(O[nt][2], O[nt][3]);
        }
    }
}

// ---------------------------------------------------------------------------
// Merge split-K halves.
// ---------------------------------------------------------------------------
__global__ void merge_kernel(float* __restrict__ out) {
    int idx = blockIdx.x * 256 + threadIdx.x;
    int row = idx >> 4;
    int c4  = idx & 15;
    int b = row >> 11;
    int t = row & 2047;

    float m0 = g_pm[0][b][t], m1 = g_pm[1][b][t];
    float l0 = g_pl[0][b][t], l1 = g_pl[1][b][t];
    float M  = fmaxf(m0, m1);
    float e0 = __expf(m0 - M), e1 = __expf(m1 - M);
    float inv = 1.0f / (l0 * e0 + l1 * e1);

    float4 a0 = *(const float4*)&g_po[0][b][t][c4 * 4];
    float4 a1 = *(const float4*)&g_po[1][b][t][c4 * 4];
    float4 o;
    o.x = (a0.x * e0 + a1.x * e1) * inv;
    o.y = (a0.y * e0 + a1.y * e1) * inv;
    o.z = (a0.z * e0 + a1.z * e1) * inv;
    o.w = (a0.w * e0 + a1.w * e1) * inv;
    *(float4*)&out[(size_t)row * H_ + c4 * 4] = o;
}

// ---------------------------------------------------------------------------
// Harness entry. Inputs: x [B,T,C], Wq, Wk, Wv [C,H]. Output: [B,T,H] f32.
// ---------------------------------------------------------------------------
extern "C" void kernel_launch(void* const* d_in, const int* in_sizes, int n_in,
                              void* d_out, int out_size) {
    const float* x  = (const float*)d_in[0];
    const float* Wq = (const float*)d_in[1];
    const float* Wk = (const float*)d_in[2];
    const float* Wv = (const float*)d_in[3];
    float* out = (float*)d_out;
    (void)in_sizes; (void)n_in; (void)out_size;

    cudaFuncSetAttribute(proj_kernel, cudaFuncAttributeMaxDynamicSharedMemorySize,
                         PROJ_SMEM);
    cudaFuncSetAttribute(attn_kernel, cudaFuncAttributeMaxDynamicSharedMemorySize,
                         ATTN_SMEM);

    prep_w_kernel<<<384, 256>>>(Wq, Wk, Wv);
    proj_kernel<<<128, 256, PROJ_SMEM>>>(x);
    attn_kernel<<<dim3(NPAIR, 2, B_), 256, ATTN_SMEM>>>();
    merge_kernel<<<(B_ * T_ * (H_ / 4)) / 256, 256>>>(out);
}

// round 10
// speedup vs baseline: 4.0606x; 1.4369x over previous
#include <cuda_runtime.h>
#include <cuda_bf16.h>
#include <cstdint>
#include <math.h>

#define B_ 8
#define T_ 2048
#define C_ 512
#define H_ 64
#define NQT128 (T_ / 128)     // 16 q-tiles of 128 rows
#define NPAIR (NQT128 / 2)    // 8 balanced pairs

// ---- device scratch (no allocations allowed) ----
__device__ __align__(16) __nv_bfloat16 g_whi[3][H_][C_];
__device__ __align__(16) __nv_bfloat16 g_wlo[3][H_][C_];
// projections, bf16 hi/lo. Q,K row-major [tok][h]; V transposed [h][tok].
__device__ __align__(16) __nv_bfloat16 g_qhi[B_ * T_][H_];
__device__ __align__(16) __nv_bfloat16 g_qlo[B_ * T_][H_];
__device__ __align__(16) __nv_bfloat16 g_khi[B_ * T_][H_];
__device__ __align__(16) __nv_bfloat16 g_klo[B_ * T_][H_];
__device__ __align__(16) __nv_bfloat16 g_vthi[H_][B_ * T_];
__device__ __align__(16) __nv_bfloat16 g_vtlo[H_][B_ * T_];
// split-K partials
__device__ __align__(16) float g_pm[2][B_][T_];
__device__ __align__(16) float g_pl[2][B_][T_];
__device__ __align__(16) float g_po[2][B_][T_][H_];

// ---- mma.sync helper (fragment mapping validated in R8) ----
__device__ __forceinline__ void mma_bf16(float* d, const uint32_t* a, uint32_t b0,
                                         uint32_t b1) {
    asm volatile(
        "mma.sync.aligned.m16n8k16.row.col.f32.bf16.bf16.f32 "
        "{%0,%1,%2,%3}, {%4,%5,%6,%7}, {%8,%9}, {%0,%1,%2,%3};"
        : "+f"(d[0]), "+f"(d[1]), "+f"(d[2]), "+f"(d[3])
        : "r"(a[0]), "r"(a[1]), "r"(a[2]), "r"(a[3]), "r"(b0), "r"(b1));
}
__device__ __forceinline__ uint32_t packbf2(float a, float b) {
    __nv_bfloat162 t = __floats2bfloat162_rn(a, b);
    return *(uint32_t*)&t;
}

// ---------------------------------------------------------------------------
// prep_w
// ---------------------------------------------------------------------------
__global__ void prep_w_kernel(const float* __restrict__ Wq,
                              const float* __restrict__ Wk,
                              const float* __restrict__ Wv) {
    int idx = blockIdx.x * 256 + threadIdx.x;
    int o = idx >> 15;
    int n = (idx >> 9) & 63;
    int k = idx & 511;
    const float* W = (o == 0) ? Wq : ((o == 1) ? Wk : Wv);
    float v = W[(size_t)k * H_ + n];
    __nv_bfloat16 hi = __float2bfloat16(v);
    __nv_bfloat16 lo = __float2bfloat16(v - __bfloat162float(hi));
    g_whi[o][n][k] = hi;
    g_wlo[o][n][k] = lo;
}

// ---------------------------------------------------------------------------
// Projection: R8/R9 mma engine; NEW: V-transpose staged through smem so the
// [h][tok] output is written with coalesced uint4 stores (previous epilogue
// issued 64 scattered 2-byte STGs per thread at 16KB stride).
// grid = 128, block = 256 (8 warps), dynamic smem = 92160 B
// ---------------------------------------------------------------------------
#define AP 72
#define SM_AHI 0
#define SM_ALO (128 * AP * 2)
#define SM_BT  (2 * 128 * AP * 2)
#define BT_SZ  (64 * AP * 2)
#define PROJ_SMEM (SM_BT + 6 * BT_SZ)
#define VSP 136   // V staging row pad (272B rows, 16B aligned)

__global__ void __launch_bounds__(256, 1) proj_kernel(const float* __restrict__ x) {
    extern __shared__ __align__(16) char smem[];
    const int tid = threadIdx.x;
    const int wid = tid >> 5;
    const int lane = tid & 31;
    const int g = lane >> 2;
    const int tq = lane & 3;
    const int rowBase = blockIdx.x * 128;

    float d[3][8][4];
    #pragma unroll
    for (int o = 0; o < 3; o++)
        #pragma unroll
        for (int nt = 0; nt < 8; nt++)
            #pragma unroll
            for (int r = 0; r < 4; r++) d[o][nt][r] = 0.0f;

    for (int c = 0; c < 8; c++) {
        for (int i = tid; i < 128 * 16; i += 256) {
            int r = i >> 4, q4 = i & 15;
            float4 v = *(const float4*)&x[(size_t)(rowBase + r) * C_ + c * 64 + q4 * 4];
            __nv_bfloat16 h0 = __float2bfloat16(v.x), h1 = __float2bfloat16(v.y);
            __nv_bfloat16 h2 = __float2bfloat16(v.z), h3 = __float2bfloat16(v.w);
            float l0 = v.x - __bfloat162float(h0), l1 = v.y - __bfloat162float(h1);
            float l2 = v.z - __bfloat162float(h2), l3 = v.w - __bfloat162float(h3);
            uint32_t off = (uint32_t)(r * AP + q4 * 4) * 2;
            __nv_bfloat162 hA; hA.x = h0; hA.y = h1;
            __nv_bfloat162 hB; hB.x = h2; hB.y = h3;
            *(uint2*)(smem + SM_AHI + off) = make_uint2(*(uint32_t*)&hA, *(uint32_t*)&hB);
            *(uint2*)(smem + SM_ALO + off) = make_uint2(packbf2(l0, l1), packbf2(l2, l3));
        }
        for (int i = tid; i < 6 * 512; i += 256) {
            int t = i >> 9, rem = i & 511;
            int n = rem >> 3, q8 = rem & 7;
            int o = (t >= 3) ? (t - 3) : t;
            const __nv_bfloat16* src = (t >= 3) ? &g_wlo[o][n][c * 64 + q8 * 8]
                                                : &g_whi[o][n][c * 64 + q8 * 8];
            *(uint4*)(smem + SM_BT + t * BT_SZ + (uint32_t)(n * AP + q8 * 8) * 2) =
                *(const uint4*)src;
        }
        __syncthreads();

        uint32_t aHi[4][4], aLo[4][4];
        {
            const int r0 = wid * 16 + g;
            #pragma unroll
            for (int ks = 0; ks < 4; ks++) {
                const int k0 = ks * 16 + tq * 2;
                uint32_t o00 = (uint32_t)(r0 * AP + k0) * 2;
                uint32_t o10 = (uint32_t)((r0 + 8) * AP + k0) * 2;
                aHi[ks][0] = *(const uint32_t*)(smem + SM_AHI + o00);
                aHi[ks][1] = *(const uint32_t*)(smem + SM_AHI + o10);
                aHi[ks][2] = *(const uint32_t*)(smem + SM_AHI + o00 + 16);
                aHi[ks][3] = *(const uint32_t*)(smem + SM_AHI + o10 + 16);
                aLo[ks][0] = *(const uint32_t*)(smem + SM_ALO + o00);
                aLo[ks][1] = *(const uint32_t*)(smem + SM_ALO + o10);
                aLo[ks][2] = *(const uint32_t*)(smem + SM_ALO + o00 + 16);
                aLo[ks][3] = *(const uint32_t*)(smem + SM_ALO + o10 + 16);
            }
        }

        #pragma unroll
        for (int o = 0; o < 3; o++) {
            const char* bHi = smem + SM_BT + o * BT_SZ;
            const char* bLo = smem + SM_BT + (o + 3) * BT_SZ;
            #pragma unroll
            for (int ks = 0; ks < 4; ks++) {
                const int k0 = ks * 16 + tq * 2;
                uint32_t bf[8][2];
                #pragma unroll
                for (int nt = 0; nt < 8; nt++) {
                    uint32_t ob = (uint32_t)((nt * 8 + g) * AP + k0) * 2;
                    bf[nt][0] = *(const uint32_t*)(bHi + ob);
                    bf[nt][1] = *(const uint32_t*)(bHi + ob + 16);
                }
                #pragma unroll
                for (int nt = 0; nt < 8; nt++) {
                    mma_bf16(d[o][nt], aHi[ks], bf[nt][0], bf[nt][1]);
                    mma_bf16(d[o][nt], aLo[ks], bf[nt][0], bf[nt][1]);
                }
                #pragma unroll
                for (int nt = 0; nt < 8; nt++) {
                    uint32_t ob = (uint32_t)((nt * 8 + g) * AP + k0) * 2;
                    bf[nt][0] = *(const uint32_t*)(bLo + ob);
                    bf[nt][1] = *(const uint32_t*)(bLo + ob + 16);
                }
                #pragma unroll
                for (int nt = 0; nt < 8; nt++)
                    mma_bf16(d[o][nt], aHi[ks], bf[nt][0], bf[nt][1]);
            }
        }
        __syncthreads();
    }

    // ---- epilogue: Q,K bf16 hi/lo (packed u32 row-major) ----
    const size_t r0 = (size_t)(rowBase + wid * 16 + g);
    #pragma unroll
    for (int o = 0; o < 2; o++) {
        __nv_bfloat16 (*dsthi)[H_] = o ? g_khi : g_qhi;
        __nv_bfloat16 (*dstlo)[H_] = o ? g_klo : g_qlo;
        #pragma unroll
        for (int nt = 0; nt < 8; nt++) {
            int col = nt * 8 + tq * 2;
            #pragma unroll
            for (int h = 0; h < 2; h++) {
                float v0 = d[o][nt][h * 2], v1 = d[o][nt][h * 2 + 1];
                __nv_bfloat16 h0 = __float2bfloat16(v0), h1 = __float2bfloat16(v1);
                float l0 = v0 - __bfloat162float(h0), l1 = v1 - __bfloat162float(h1);
                __nv_bfloat162 hp; hp.x = h0; hp.y = h1;
                *(uint32_t*)&dsthi[r0 + h * 8][col] = *(uint32_t*)&hp;
                *(uint32_t*)&dstlo[r0 + h * 8][col] = packbf2(l0, l1);
            }
        }
    }
    // ---- V: stage transpose in smem (reuses dead B-tile region), then
    //      coalesced row stores to g_vt{hi,lo}[h][tok] ----
    {
        __nv_bfloat16 (*sVhi)[VSP] = (__nv_bfloat16(*)[VSP])(smem + SM_BT);
        __nv_bfloat16 (*sVlo)[VSP] =
            (__nv_bfloat16(*)[VSP])(smem + SM_BT + 64 * VSP * 2);
        int tl0 = wid * 16 + g;
        #pragma unroll
        for (int nt = 0; nt < 8; nt++) {
            #pragma unroll
            for (int j = 0; j < 4; j++) {
                int col = nt * 8 + tq * 2 + (j & 1);
                int tl = tl0 + (j >> 1) * 8;
                float v = d[2][nt][j];
                __nv_bfloat16 hi = __float2bfloat16(v);
                sVhi[col][tl] = hi;
                sVlo[col][tl] = __float2bfloat16(v - __bfloat162float(hi));
            }
        }
        __syncthreads();
        for (int i = tid; i < 64 * 16; i += 256) {
            int h = i >> 4, q8 = i & 15;
            *(uint4*)&g_vthi[h][rowBase + q8 * 8] = *(const uint4*)&sVhi[h][q8 * 8];
            *(uint4*)&g_vtlo[h][rowBase + q8 * 8] = *(const uint4*)&sVlo[h][q8 * 8];
        }
    }
}

// ---------------------------------------------------------------------------
// Flash attention, mma.sync + DOUBLE-BUFFERED K/V tiles.
// Per tile: STS(prefetched regs -> buf cur); LDG(next tile -> regs);
// one __syncthreads; compute. WAR on buf(1-cur) is guarded by the previous
// iteration's sync (audited).
// smem: 2 x [Khi|Klo|Vhi|Vlo][64][72]bf16 (36864 each) + sP 18432 = 92160.
// grid=(8,2,8), block=256.
// ---------------------------------------------------------------------------
#define APB 72
#define ROWB (APB * 2)
#define TILE_SZ 36864           // 4 sub-tiles x 9216
#define SK_HI 0
#define SK_LO 9216
#define SV_HI 18432
#define SV_LO 27648
#define SP_OFF (2 * TILE_SZ)    // 73728
#define ATTN_SMEM (SP_OFF + 128 * ROWB)   // 92160

__device__ __forceinline__ void attn_ld_tile(uint4* pf, int b, int kt, int tid) {
    #pragma unroll
    for (int j = 0; j < 8; j++) {
        int i = tid + j * 256;
        int which = i >> 9, rem = i & 511;
        int r = rem >> 3, q8 = rem & 7;
        const __nv_bfloat16* src;
        if      (which == 0) src = &g_khi[(size_t)b * T_ + kt * 64 + r][q8 * 8];
        else if (which == 1) src = &g_klo[(size_t)b * T_ + kt * 64 + r][q8 * 8];
        else if (which == 2) src = &g_vthi[r][(size_t)b * T_ + kt * 64 + q8 * 8];
        else                 src = &g_vtlo[r][(size_t)b * T_ + kt * 64 + q8 * 8];
        pf[j] = *(const uint4*)src;
    }
}
__device__ __forceinline__ void attn_st_tile(const uint4* pf, char* buf, int tid) {
    #pragma unroll
    for (int j = 0; j < 8; j++) {
        int i = tid + j * 256;
        int which = i >> 9, rem = i & 511;
        int r = rem >> 3, q8 = rem & 7;
        *(uint4*)(buf + which * 9216 + r * ROWB + q8 * 16) = pf[j];
    }
}

__global__ void __launch_bounds__(256, 1) attn_kernel() {
    extern __shared__ __align__(16) char sm[];
    const int pair = blockIdx.x;
    const int hf   = blockIdx.y;
    const int b    = blockIdx.z;
    const int tid  = threadIdx.x;
    const int wid  = tid >> 5;
    const int lane = tid & 31;
    const int g    = lane >> 2;
    const int tq   = lane & 3;

    for (int side = 0; side < 2; side++) {
        const int qt = side ? (NQT128 - 1 - pair) : pair;
        const int row0 = qt * 128 + wid * 16 + g;
        const int row1 = row0 + 8;
        const size_t tok0 = (size_t)b * T_ + row0;

        uint32_t qhi[4][4], qlo[4][4];
        #pragma unroll
        for (int ks = 0; ks < 4; ks++) {
            const int k0 = ks * 16 + tq * 2;
            qhi[ks][0] = *(const uint32_t*)&g_qhi[tok0][k0];
            qhi[ks][1] = *(const uint32_t*)&g_qhi[tok0 + 8][k0];
            qhi[ks][2] = *(const uint32_t*)&g_qhi[tok0][k0 + 8];
            qhi[ks][3] = *(const uint32_t*)&g_qhi[tok0 + 8][k0 + 8];
            qlo[ks][0] = *(const uint32_t*)&g_qlo[tok0][k0];
            qlo[ks][1] = *(const uint32_t*)&g_qlo[tok0 + 8][k0];
            qlo[ks][2] = *(const uint32_t*)&g_qlo[tok0][k0 + 8];
            qlo[ks][3] = *(const uint32_t*)&g_qlo[tok0 + 8][k0 + 8];
        }

        float O[8][4];
        #pragma unroll
        for (int nt = 0; nt < 8; nt++)
            #pragma unroll
            for (int r = 0; r < 4; r++) O[nt][r] = 0.0f;
        float m0 = -1e30f, m1 = -1e30f, l0 = 0.0f, l1 = 0.0f;

        const int kt0 = hf ? (qt + 1)     : 0;
        const int kt1 = hf ? (2 * qt + 2) : (qt + 1);
        const int ntl = kt1 - kt0;

        uint4 pf[8];
        attn_ld_tile(pf, b, kt0, tid);

        for (int it = 0; it < ntl; it++) {
            const int kt = kt0 + it;
            char* buf = sm + (it & 1) * TILE_SZ;
            attn_st_tile(pf, buf, tid);
            if (it + 1 < ntl) attn_ld_tile(pf, b, kt + 1, tid);
            __syncthreads();

            // ---- S = Q K^T, 3-term split ----
            float s[8][4];
            #pragma unroll
            for (int nt = 0; nt < 8; nt++)
                #pragma unroll
                for (int r = 0; r < 4; r++) s[nt][r] = 0.0f;
            #pragma unroll
            for (int ks = 0; ks < 4; ks++) {
                const int kb = (ks * 16 + tq * 2) * 2;
                #pragma unroll
                for (int nt = 0; nt < 8; nt++) {
                    const char* rh = buf + SK_HI + (nt * 8 + g) * ROWB;
                    uint32_t b0 = *(const uint32_t*)(rh + kb);
                    uint32_t b1 = *(const uint32_t*)(rh + kb + 16);
                    mma_bf16(s[nt], qhi[ks], b0, b1);
                    mma_bf16(s[nt], qlo[ks], b0, b1);
                    const char* rl = buf + SK_LO + (nt * 8 + g) * ROWB;
                    uint32_t c0 = *(const uint32_t*)(rl + kb);
                    uint32_t c1 = *(const uint32_t*)(rl + kb + 16);
                    mma_bf16(s[nt], qhi[ks], c0, c1);
                }
            }

            if (kt >= 2 * qt) {
                #pragma unroll
                for (int nt = 0; nt < 8; nt++) {
                    int col = kt * 64 + nt * 8 + tq * 2;
                    if (col > row0)     s[nt][0] = -1e30f;
                    if (col + 1 > row0) s[nt][1] = -1e30f;
                    if (col > row1)     s[nt][2] = -1e30f;
                    if (col + 1 > row1) s[nt][3] = -1e30f;
                }
            }

            // ---- online softmax on fragments ----
            float a0 = -1e30f, a1 = -1e30f;
            #pragma unroll
            for (int nt = 0; nt < 8; nt++) {
                a0 = fmaxf(a0, fmaxf(s[nt][0], s[nt][1]));
                a1 = fmaxf(a1, fmaxf(s[nt][2], s[nt][3]));
            }
            a0 = fmaxf(a0, __shfl_xor_sync(0xffffffffu, a0, 1));
            a0 = fmaxf(a0, __shfl_xor_sync(0xffffffffu, a0, 2));
            a1 = fmaxf(a1, __shfl_xor_sync(0xffffffffu, a1, 1));
            a1 = fmaxf(a1, __shfl_xor_sync(0xffffffffu, a1, 2));
            float nm0 = fmaxf(m0, a0), nm1 = fmaxf(m1, a1);
            float sc0 = __expf(m0 - nm0), sc1 = __expf(m1 - nm1);
            float rs0 = 0.0f, rs1 = 0.0f;
            char* prow0 = sm + SP_OFF + (wid * 16 + g) * ROWB;
            #pragma unroll
            for (int nt = 0; nt < 8; nt++) {
                float p00 = __expf(s[nt][0] - nm0), p01 = __expf(s[nt][1] - nm0);
                float p10 = __expf(s[nt][2] - nm1), p11 = __expf(s[nt][3] - nm1);
                __nv_bfloat162 r0p = __floats2bfloat162_rn(p00, p01);
                __nv_bfloat162 r1p = __floats2bfloat162_rn(p10, p11);
                rs0 += __bfloat162float(r0p.x) + __bfloat162float(r0p.y);
                rs1 += __bfloat162float(r1p.x) + __bfloat162float(r1p.y);
                *(uint32_t*)(prow0 + (nt * 8 + tq * 2) * 2) = *(uint32_t*)&r0p;
                *(uint32_t*)(prow0 + 8 * ROWB + (nt * 8 + tq * 2) * 2) = *(uint32_t*)&r1p;
            }
            rs0 += __shfl_xor_sync(0xffffffffu, rs0, 1);
            rs0 += __shfl_xor_sync(0xffffffffu, rs0, 2);
            rs1 += __shfl_xor_sync(0xffffffffu, rs1, 1);
            rs1 += __shfl_xor_sync(0xffffffffu, rs1, 2);
            l0 = l0 * sc0 + rs0; m0 = nm0;
            l1 = l1 * sc1 + rs1; m1 = nm1;
            #pragma unroll
            for (int nt = 0; nt < 8; nt++) {
                O[nt][0] *= sc0; O[nt][1] *= sc0;
                O[nt][2] *= sc1; O[nt][3] *= sc1;
            }
            __syncwarp();   // sP rows are warp-local

            // ---- O += P @ V (V hi + V lo) ----
            #pragma unroll
            for (int ks = 0; ks < 4; ks++) {
                const int kb = (ks * 16 + tq * 2) * 2;
                uint32_t pa[4];
                const char* pr = sm + SP_OFF + (wid * 16 + g) * ROWB;
                pa[0] = *(const uint32_t*)(pr + kb);
                pa[1] = *(const uint32_t*)(pr + 8 * ROWB + kb);
                pa[2] = *(const uint32_t*)(pr + kb + 16);
                pa[3] = *(const uint32_t*)(pr + 8 * ROWB + kb + 16);
                #pragma unroll
                for (int nt = 0; nt < 8; nt++) {
                    const char* vh = buf + SV_HI + (nt * 8 + g) * ROWB;
                    uint32_t b0 = *(const uint32_t*)(vh + kb);
                    uint32_t b1 = *(const uint32_t*)(vh + kb + 16);
                    mma_bf16(O[nt], pa, b0, b1);
                    const char* vl = buf + SV_LO + (nt * 8 + g) * ROWB;
                    b0 = *(const uint32_t*)(vl + kb);
                    b1 = *(const uint32_t*)(vl + kb + 16);
                    mma_bf16(O[nt], pa, b0, b1);
                }
            }
            // no end-of-iter sync needed: next write to this buffer is 2
            // iterations away, guarded by the next iteration's top sync.
        }
        __syncthreads();   // before next side reuses buffers

        if (tq == 0) {
            g_pm[hf][b][row0] = m0; g_pl[hf][b][row0] = l0;
            g_pm[hf][b][row1] = m1; g_pl[hf][b][row1] = l1;
        }
        #pragma unroll
        for (int nt = 0; nt < 8; nt++) {
            int col = nt * 8 + tq * 2;
            *(float2*)&g_po[hf][b][row0][col] = make_float2(O[nt][0], O[nt][1]);
            *(float2*)&g_po[hf][b][row1][col] = make_float2(O[nt][2], O[nt][3]);
        }
    }
}

// ---------------------------------------------------------------------------
// Merge split-K halves.
// ---------------------------------------------------------------------------
__global__ void merge_kernel(float* __restrict__ out) {
    int idx = blockIdx.x * 256 + threadIdx.x;
    int row = idx >> 4;
    int c4  = idx & 15;
    int b = row >> 11;
    int t = row & 2047;

    float m0 = g_pm[0][b][t], m1 = g_pm[1][b][t];
    float l0 = g_pl[0][b][t], l1 = g_pl[1][b][t];
    float M  = fmaxf(m0, m1);
    float e0 = __expf(m0 - M), e1 = __expf(m1 - M);
    float inv = 1.0f / (l0 * e0 + l1 * e1);

    float4 a0 = *(const float4*)&g_po[0][b][t][c4 * 4];
    float4 a1 = *(const float4*)&g_po[1][b][t][c4 * 4];
    float4 o;
    o.x = (a0.x * e0 + a1.x * e1) * inv;
    o.y = (a0.y * e0 + a1.y * e1) * inv;
    o.z = (a0.z * e0 + a1.z * e1) * inv;
    o.w = (a0.w * e0 + a1.w * e1) * inv;
    *(float4*)&out[(size_t)row * H_ + c4 * 4] = o;
}

// ---------------------------------------------------------------------------
// Harness entry. Inputs: x [B,T,C], Wq, Wk, Wv [C,H]. Output: [B,T,H] f32.
// ---------------------------------------------------------------------------
extern "C" void kernel_launch(void* const* d_in, const int* in_sizes, int n_in,
                              void* d_out, int out_size) {
    const float* x  = (const float*)d_in[0];
    const float* Wq = (const float*)d_in[1];
    const float* Wk = (const float*)d_in[2];
    const float* Wv = (const float*)d_in[3];
    float* out = (float*)d_out;
    (void)in_sizes; (void)n_in; (void)out_size;

    cudaFuncSetAttribute(proj_kernel, cudaFuncAttributeMaxDynamicSharedMemorySize,
                         PROJ_SMEM);
    cudaFuncSetAttribute(attn_kernel, cudaFuncAttributeMaxDynamicSharedMemorySize,
                         ATTN_SMEM);

    prep_w_kernel<<<384, 256>>>(Wq, Wk, Wv);
    proj_kernel<<<128, 256, PROJ_SMEM>>>(x);
    attn_kernel<<<dim3(NPAIR, 2, B_), 256, ATTN_SMEM>>>();
    merge_kernel<<<(B_ * T_ * (H_ / 4)) / 256, 256>>>(out);
}